// round 8
// baseline (speedup 1.0000x reference)
#include <cuda_runtime.h>
#include <cuda_bf16.h>
#include <cstdint>

// Problem constants
constexpr int B_  = 32;
constexpr int H_  = 12;
constexpr int W_  = 256;
constexpr int C_  = 256;
constexpr int HS_ = 4;            // H / SPLIT
constexpr int N_  = HS_ * W_;     // 1024 flattened spatial
constexpr int FC_ = 96;           // SPLIT * Cf
constexpr int HC_ = 768;          // SPLIT * C
constexpr int P_  = B_ * H_ * W_; // 98304 pixels

// Scratch (device globals)
__device__ __nv_bfloat16 g_xhi[(size_t)P_ * C_];        // 50 MB
__device__ __nv_bfloat16 g_xlo[(size_t)P_ * C_];        // 50 MB
__device__ __nv_bfloat16 g_Wthi[320 * 256];             // [j][k] transposed concat
__device__ __nv_bfloat16 g_Wtlo[320 * 256];
__device__ __nv_bfloat16 g_fhi[(size_t)B_ * N_ * FC_];  // 6.3 MB each
__device__ __nv_bfloat16 g_flo[(size_t)B_ * N_ * FC_];
__device__ __nv_bfloat16 g_ghi[(size_t)B_ * N_ * FC_];
__device__ __nv_bfloat16 g_glo[(size_t)B_ * N_ * FC_];
__device__ __nv_bfloat16 g_beta[(size_t)B_ * N_ * N_];  // 64 MB  [b][n][m]
__device__ __nv_bfloat16 g_hT[(size_t)B_ * HC_ * N_];   // 48 MB  [b][c][n]

// ============================ PTX helpers ==================================
__device__ __forceinline__ uint32_t smem_u32(const void* p) {
    uint32_t a;
    asm("{ .reg .u64 t; cvta.to.shared.u64 t, %1; cvt.u32.u64 %0, t; }"
        : "=r"(a) : "l"(p));
    return a;
}
#define CP16(s, g) \
    asm volatile("cp.async.cg.shared.global [%0], [%1], 16;" \
        :: "r"(s), "l"(g) : "memory")
#define CPCOMMIT() asm volatile("cp.async.commit_group;" ::: "memory")
#define CPWAIT(n)  asm volatile("cp.async.wait_group %0;" :: "n"(n) : "memory")

__device__ __forceinline__ void ldsm_x4(uint32_t& r0, uint32_t& r1,
                                        uint32_t& r2, uint32_t& r3, uint32_t addr) {
    asm volatile("ldmatrix.sync.aligned.m8n8.x4.shared.b16 {%0,%1,%2,%3}, [%4];"
        : "=r"(r0), "=r"(r1), "=r"(r2), "=r"(r3) : "r"(addr));
}
__device__ __forceinline__ void mma_bf16(float* c, const uint32_t* a, const uint32_t* b) {
    asm volatile("mma.sync.aligned.m16n8k16.row.col.f32.bf16.bf16.f32 "
        "{%0,%1,%2,%3}, {%4,%5,%6,%7}, {%8,%9}, {%0,%1,%2,%3};"
        : "+f"(c[0]), "+f"(c[1]), "+f"(c[2]), "+f"(c[3])
        : "r"(a[0]), "r"(a[1]), "r"(a[2]), "r"(a[3]), "r"(b[0]), "r"(b[1]));
}
// smem tile: 64B rows (32 bf16), 4x16B chunks/row, XOR swizzle for ldmatrix
__device__ __forceinline__ uint32_t swz(int r, int c) {
    return (uint32_t)(r * 64 + ((c ^ ((r >> 1) & 3)) << 4));
}
__device__ __forceinline__ void split2(float v, __nv_bfloat16& hi, __nv_bfloat16& lo) {
    hi = __float2bfloat16(v);
    lo = __float2bfloat16(v - __bfloat162float(hi));
}

// ---------------------------------------------------------------------------
// Kernel 0a: split x into bf16 hi/lo
// ---------------------------------------------------------------------------
__global__ __launch_bounds__(256) void k_split_x(const float* __restrict__ x)
{
    size_t gid = (size_t)blockIdx.x * 256 + threadIdx.x;   // float4 index
    float4 v = reinterpret_cast<const float4*>(x)[gid];
    __nv_bfloat16 h0, h1, h2, h3, l0, l1, l2, l3;
    split2(v.x, h0, l0); split2(v.y, h1, l1);
    split2(v.z, h2, l2); split2(v.w, h3, l3);
    uint2 hu, lu;
    reinterpret_cast<__nv_bfloat162*>(&hu)[0] = __nv_bfloat162(h0, h1);
    reinterpret_cast<__nv_bfloat162*>(&hu)[1] = __nv_bfloat162(h2, h3);
    reinterpret_cast<__nv_bfloat162*>(&lu)[0] = __nv_bfloat162(l0, l1);
    reinterpret_cast<__nv_bfloat162*>(&lu)[1] = __nv_bfloat162(l2, l3);
    reinterpret_cast<uint2*>(g_xhi)[gid] = hu;
    reinterpret_cast<uint2*>(g_xlo)[gid] = lu;
}

// ---------------------------------------------------------------------------
// Kernel 0b: build transposed split concat weight Wt[j][k], j in [0,320)
// ---------------------------------------------------------------------------
__global__ __launch_bounds__(256) void k_split_w(
    const float* __restrict__ Wf, const float* __restrict__ Wg,
    const float* __restrict__ Wh)
{
    const int j = blockIdx.x;
    const int k = threadIdx.x;
    float v;
    if (j < 256)      v = Wh[k * 256 + j];
    else if (j < 288) v = Wf[k * 32 + (j - 256)];
    else              v = Wg[k * 32 + (j - 288)];
    __nv_bfloat16 hi, lo;
    split2(v, hi, lo);
    g_Wthi[j * 256 + k] = hi;
    g_Wtlo[j * 256 + k] = lo;
}

// ---------------------------------------------------------------------------
// Kernel 1a: h projection, 1-pass bf16 HMMA.
// Tile 128(p) x 64(c), K=256. 8 warps (4m x 2n).
// Epilogue: transpose in smem -> coalesced g_hT write.
// ---------------------------------------------------------------------------
constexpr int PH_STAGE = 12288;   // Ah 8K + Bh 4K
constexpr int PH_STGS  = 3;
constexpr int TS_ = 136;          // transpose staging row pitch (bf16)

__global__ __launch_bounds__(256) void k_proj_h()
{
    extern __shared__ char smem[];
    const uint32_t sbase = smem_u32(smem);
    const int tid  = threadIdx.x;
    const int wid  = tid >> 5;
    const int lane = tid & 31;
    const int wm   = wid & 3;
    const int wn   = wid >> 2;
    const int cBase = blockIdx.x * 64;     // 0..3 -> channels 0..255
    const int pBase = blockIdx.y * 128;

    const __nv_bfloat16* gAh = g_xhi + (size_t)pBase * 256;
    const __nv_bfloat16* gBh = g_Wthi + (size_t)cBase * 256;

    const int arow = tid >> 2, ac = tid & 3;
    auto issue = [&](int slot, int kc) {
        const uint32_t st = sbase + slot * PH_STAGE;
#pragma unroll
        for (int i = 0; i < 2; i++) {
            int idx = i * 256 + tid;
            int r = idx >> 2, c = idx & 3;
            CP16(st + swz(r, c), gAh + (size_t)r * 256 + kc * 32 + c * 8);
        }
        if (arow < 64)
            CP16(st + 8192 + swz(arow, ac), gBh + (size_t)arow * 256 + kc * 32 + ac * 8);
    };

    float acc[2][4][4];
#pragma unroll
    for (int mt = 0; mt < 2; mt++)
#pragma unroll
        for (int nt = 0; nt < 4; nt++)
#pragma unroll
            for (int j = 0; j < 4; j++) acc[mt][nt][j] = 0.f;

    issue(0, 0); CPCOMMIT();
    issue(1, 1); CPCOMMIT();

    for (int kc = 0; kc < 8; kc++) {
        if (kc + 2 < 8) {
            issue((kc + 2) % PH_STGS, kc + 2); CPCOMMIT();
            CPWAIT(2);
        } else {
            CPWAIT(0);
        }
        __syncthreads();
        const uint32_t st = sbase + (kc % PH_STGS) * PH_STAGE;
#pragma unroll
        for (int ks = 0; ks < 2; ks++) {
            uint32_t ah[2][4];
#pragma unroll
            for (int mt = 0; mt < 2; mt++) {
                int row = wm * 32 + mt * 16 + ((lane >> 3) & 1) * 8 + (lane & 7);
                int ch  = ks * 2 + (lane >> 4);
                ldsm_x4(ah[mt][0], ah[mt][1], ah[mt][2], ah[mt][3], st + swz(row, ch));
            }
            uint32_t bh[4][2];
#pragma unroll
            for (int p = 0; p < 2; p++) {
                int row = wn * 32 + p * 16 + (lane >> 4) * 8 + (lane & 7);
                int ch  = ks * 2 + ((lane >> 3) & 1);
                uint32_t r0, r1, r2, r3;
                ldsm_x4(r0, r1, r2, r3, st + 8192 + swz(row, ch));
                bh[2 * p][0] = r0; bh[2 * p][1] = r1;
                bh[2 * p + 1][0] = r2; bh[2 * p + 1][1] = r3;
            }
#pragma unroll
            for (int mt = 0; mt < 2; mt++)
#pragma unroll
                for (int nt = 0; nt < 4; nt++)
                    mma_bf16(acc[mt][nt], ah[mt], bh[nt]);
        }
        __syncthreads();
    }

    const int gr = lane >> 2;
    const int qc = (lane & 3) * 2;
    const int bb  = pBase / (H_ * W_);
    const int rem = pBase - bb * (H_ * W_);
    const int hpx = rem >> 8;
    const int w0  = rem & 255;
    const int sg  = hpx >> 2;
    const int hr  = hpx & 3;
    const int n0  = hr * W_ + w0;

    __nv_bfloat16* ts = reinterpret_cast<__nv_bfloat16*>(smem);
#pragma unroll
    for (int mt = 0; mt < 2; mt++)
#pragma unroll
        for (int rr = 0; rr < 2; rr++) {
            int nl = wm * 32 + mt * 16 + rr * 8 + gr;
#pragma unroll
            for (int nt = 0; nt < 4; nt++) {
                int cl = wn * 32 + nt * 8 + qc;
                ts[cl * TS_ + nl]       = __float2bfloat16(acc[mt][nt][rr * 2 + 0]);
                ts[(cl + 1) * TS_ + nl] = __float2bfloat16(acc[mt][nt][rr * 2 + 1]);
            }
        }
    __syncthreads();
    const size_t hTrow0 = ((size_t)bb * HC_ + sg * 256 + cBase) * N_ + n0;
#pragma unroll
    for (int i = 0; i < 4; i++) {
        int idx = i * 256 + tid;
        int r = idx >> 4, u = idx & 15;
        uint4 v = *reinterpret_cast<const uint4*>(&ts[r * TS_ + u * 8]);
        *reinterpret_cast<uint4*>(&g_hT[hTrow0 + (size_t)r * N_ + u * 8]) = v;
    }
}

// ---------------------------------------------------------------------------
// Kernel 1b: f/g projection via 3-pass bf16 HMMA (logits precision-critical).
// ---------------------------------------------------------------------------
constexpr int PJ_STAGE = 24576;   // Ah 8K + Al 8K + Bh 4K + Bl 4K
constexpr int PJ_STGS  = 3;

__global__ __launch_bounds__(256) void k_proj_fg()
{
    extern __shared__ char smem[];
    const uint32_t sbase = smem_u32(smem);
    const int tid  = threadIdx.x;
    const int wid  = tid >> 5;
    const int lane = tid & 31;
    const int wm   = wid & 3;
    const int wn   = wid >> 2;
    const int cBase = 256;                 // f/g columns 256..319
    const int pBase = blockIdx.x * 128;

    const __nv_bfloat16* gAh = g_xhi + (size_t)pBase * 256;
    const __nv_bfloat16* gAl = g_xlo + (size_t)pBase * 256;
    const __nv_bfloat16* gBh = g_Wthi + (size_t)cBase * 256;
    const __nv_bfloat16* gBl = g_Wtlo + (size_t)cBase * 256;

    const int arow = tid >> 2, ac = tid & 3;
    auto issue = [&](int slot, int kc) {
        const uint32_t st = sbase + slot * PJ_STAGE;
        const int kOff = kc * 32 + ac * 8;
#pragma unroll
        for (int i = 0; i < 2; i++) {
            int idx = i * 256 + tid;
            int r = idx >> 2, c = idx & 3;
            int ko = kc * 32 + c * 8;
            CP16(st + swz(r, c), gAh + (size_t)r * 256 + ko);
            CP16(st + 8192 + swz(r, c), gAl + (size_t)r * 256 + ko);
        }
        if (arow < 64) {
            CP16(st + 16384 + swz(arow, ac), gBh + (size_t)arow * 256 + kOff);
            CP16(st + 20480 + swz(arow, ac), gBl + (size_t)arow * 256 + kOff);
        }
    };

    float acc[2][4][4];
#pragma unroll
    for (int mt = 0; mt < 2; mt++)
#pragma unroll
        for (int nt = 0; nt < 4; nt++)
#pragma unroll
            for (int j = 0; j < 4; j++) acc[mt][nt][j] = 0.f;

    issue(0, 0); CPCOMMIT();
    issue(1, 1); CPCOMMIT();

    for (int kc = 0; kc < 8; kc++) {
        if (kc + 2 < 8) {
            issue((kc + 2) % PJ_STGS, kc + 2); CPCOMMIT();
            CPWAIT(2);
        } else {
            CPWAIT(0);
        }
        __syncthreads();
        const uint32_t st = sbase + (kc % PJ_STGS) * PJ_STAGE;
#pragma unroll
        for (int ks = 0; ks < 2; ks++) {
            uint32_t ah[2][4], al[2][4];
#pragma unroll
            for (int mt = 0; mt < 2; mt++) {
                int row = wm * 32 + mt * 16 + ((lane >> 3) & 1) * 8 + (lane & 7);
                int ch  = ks * 2 + (lane >> 4);
                ldsm_x4(ah[mt][0], ah[mt][1], ah[mt][2], ah[mt][3], st + swz(row, ch));
                ldsm_x4(al[mt][0], al[mt][1], al[mt][2], al[mt][3], st + 8192 + swz(row, ch));
            }
            uint32_t bh[4][2], bl[4][2];
#pragma unroll
            for (int p = 0; p < 2; p++) {
                int row = wn * 32 + p * 16 + (lane >> 4) * 8 + (lane & 7);
                int ch  = ks * 2 + ((lane >> 3) & 1);
                uint32_t r0, r1, r2, r3;
                ldsm_x4(r0, r1, r2, r3, st + 16384 + swz(row, ch));
                bh[2 * p][0] = r0; bh[2 * p][1] = r1;
                bh[2 * p + 1][0] = r2; bh[2 * p + 1][1] = r3;
                ldsm_x4(r0, r1, r2, r3, st + 20480 + swz(row, ch));
                bl[2 * p][0] = r0; bl[2 * p][1] = r1;
                bl[2 * p + 1][0] = r2; bl[2 * p + 1][1] = r3;
            }
#pragma unroll
            for (int mt = 0; mt < 2; mt++)
#pragma unroll
                for (int nt = 0; nt < 4; nt++) {
                    mma_bf16(acc[mt][nt], ah[mt], bh[nt]);
                    mma_bf16(acc[mt][nt], ah[mt], bl[nt]);
                    mma_bf16(acc[mt][nt], al[mt], bh[nt]);
                }
        }
        __syncthreads();
    }

    const int gr = lane >> 2;
    const int qc = (lane & 3) * 2;
    const int bb  = pBase / (H_ * W_);
    const int rem = pBase - bb * (H_ * W_);
    const int hpx = rem >> 8;
    const int w0  = rem & 255;
    const int sg  = hpx >> 2;
    const int hr  = hpx & 3;
    const int n0  = hr * W_ + w0;

#pragma unroll
    for (int mt = 0; mt < 2; mt++)
#pragma unroll
        for (int rr = 0; rr < 2; rr++) {
            int nl = wm * 32 + mt * 16 + rr * 8 + gr;
            int n  = n0 + nl;
            size_t base = ((size_t)bb * N_ + n) * FC_ + sg * 32;
#pragma unroll
            for (int nt = 0; nt < 4; nt++) {
                int j = cBase + wn * 32 + nt * 8 + qc;   // 256..319
                float v0 = acc[mt][nt][rr * 2 + 0];
                float v1 = acc[mt][nt][rr * 2 + 1];
                __nv_bfloat16 h0, h1, l0, l1;
                split2(v0, h0, l0); split2(v1, h1, l1);
                __nv_bfloat162 hv(h0, h1), lv(l0, l1);
                if (j < 288) {
                    size_t idx = base + (j - 256);
                    *reinterpret_cast<__nv_bfloat162*>(&g_fhi[idx]) = hv;
                    *reinterpret_cast<__nv_bfloat162*>(&g_flo[idx]) = lv;
                } else {
                    size_t idx = base + (j - 288);
                    *reinterpret_cast<__nv_bfloat162*>(&g_ghi[idx]) = hv;
                    *reinterpret_cast<__nv_bfloat162*>(&g_glo[idx]) = lv;
                }
            }
        }
}

// ---------------------------------------------------------------------------
// Kernel 2: FUSED score + softmax. One CTA = 32 rows x full 1024 cols of s.
// Scores strip lives in smem (32 x 1032 fp32); B (f) streamed in 128-col
// chunks; 3-pass bf16 HMMA; softmax in smem; writes bf16 beta only.
// Warps: 2m (16 rows) x 4n (32 cols each) per chunk.
// ---------------------------------------------------------------------------
constexpr int SS_PITCH = 1032;                        // fp32 pitch, pad vs conflicts
constexpr int FS_A   = 32 * SS_PITCH * 4;             // 132096: A buffers after scores
constexpr int FS_B   = FS_A + 12288;                  // Ah 6K + Al 6K
constexpr int FS_RED = FS_B + 49152;                  // Bh 24K + Bl 24K
constexpr int FS_TOTAL = FS_RED + 128;

__global__ __launch_bounds__(256) void k_fused_attn()
{
    extern __shared__ char smem[];
    float* scores = reinterpret_cast<float*>(smem);
    float* red    = reinterpret_cast<float*>(smem + FS_RED);
    const uint32_t sbase = smem_u32(smem);
    const uint32_t aHi = sbase + FS_A, aLo = aHi + 6144;
    const uint32_t bHi = sbase + FS_B, bLo = bHi + 24576;

    const int tid  = threadIdx.x;
    const int wid  = tid >> 5;
    const int lane = tid & 31;
    const int wm   = wid & 1;      // 2 m-warps x 16 rows
    const int wn   = wid >> 1;     // 4 n-warps x 32 cols
    const int b     = blockIdx.y;
    const int nBase = blockIdx.x * 32;

    const __nv_bfloat16* gAh = g_ghi + ((size_t)b * N_ + nBase) * FC_;
    const __nv_bfloat16* gAl = g_glo + ((size_t)b * N_ + nBase) * FC_;
    const __nv_bfloat16* gBh = g_fhi + (size_t)b * N_ * FC_;
    const __nv_bfloat16* gBl = g_flo + (size_t)b * N_ * FC_;

    // Load A (g rows nBase..+32, hi/lo, 3 k-subtiles)
#pragma unroll
    for (int t = 0; t < 3; t++) {
        if (tid < 128) {
            int r = tid >> 2, c = tid & 3;
            CP16(aHi + t * 2048 + swz(r, c), gAh + (size_t)r * FC_ + t * 32 + c * 8);
        } else {
            int t2 = tid - 128;
            int r = t2 >> 2, c = t2 & 3;
            CP16(aLo + t * 2048 + swz(r, c), gAl + (size_t)r * FC_ + t * 32 + c * 8);
        }
    }
    CPCOMMIT();

    const int gr = lane >> 2;
    const int qc = (lane & 3) * 2;

    for (int mc = 0; mc < 8; mc++) {
        // Load B chunk (f rows mc*128..+128, hi/lo, 3 subtiles)
#pragma unroll
        for (int t = 0; t < 3; t++)
#pragma unroll
            for (int i = 0; i < 2; i++) {
                int idx = i * 256 + tid;
                int r = idx >> 2, c = idx & 3;
                size_t go = (size_t)(mc * 128 + r) * FC_ + t * 32 + c * 8;
                CP16(bHi + t * 8192 + swz(r, c), gBh + go);
                CP16(bLo + t * 8192 + swz(r, c), gBl + go);
            }
        CPCOMMIT(); CPWAIT(0);
        __syncthreads();

        float acc[4][4];
#pragma unroll
        for (int nt = 0; nt < 4; nt++)
#pragma unroll
            for (int j = 0; j < 4; j++) acc[nt][j] = 0.f;

#pragma unroll
        for (int t = 0; t < 3; t++) {
#pragma unroll
            for (int ks = 0; ks < 2; ks++) {
                uint32_t ah[4], al[4];
                {
                    int row = wm * 16 + ((lane >> 3) & 1) * 8 + (lane & 7);
                    int ch  = ks * 2 + (lane >> 4);
                    ldsm_x4(ah[0], ah[1], ah[2], ah[3], aHi + t * 2048 + swz(row, ch));
                    ldsm_x4(al[0], al[1], al[2], al[3], aLo + t * 2048 + swz(row, ch));
                }
                uint32_t bh[4][2], bl[4][2];
#pragma unroll
                for (int p = 0; p < 2; p++) {
                    int row = wn * 32 + p * 16 + (lane >> 4) * 8 + (lane & 7);
                    int ch  = ks * 2 + ((lane >> 3) & 1);
                    uint32_t r0, r1, r2, r3;
                    ldsm_x4(r0, r1, r2, r3, bHi + t * 8192 + swz(row, ch));
                    bh[2 * p][0] = r0; bh[2 * p][1] = r1;
                    bh[2 * p + 1][0] = r2; bh[2 * p + 1][1] = r3;
                    ldsm_x4(r0, r1, r2, r3, bLo + t * 8192 + swz(row, ch));
                    bl[2 * p][0] = r0; bl[2 * p][1] = r1;
                    bl[2 * p + 1][0] = r2; bl[2 * p + 1][1] = r3;
                }
#pragma unroll
                for (int nt = 0; nt < 4; nt++) {
                    mma_bf16(acc[nt], ah, bh[nt]);
                    mma_bf16(acc[nt], ah, bl[nt]);
                    mma_bf16(acc[nt], al, bh[nt]);
                }
            }
        }

        // Scatter chunk scores to smem strip
#pragma unroll
        for (int rr = 0; rr < 2; rr++) {
            int m = wm * 16 + rr * 8 + gr;
#pragma unroll
            for (int nt = 0; nt < 4; nt++) {
                int col = mc * 128 + wn * 32 + nt * 8 + qc;
                *reinterpret_cast<float2*>(&scores[m * SS_PITCH + col]) =
                    make_float2(acc[nt][rr * 2], acc[nt][rr * 2 + 1]);
            }
        }
        __syncthreads();
    }

    // Softmax: 8 threads per row, each covers 128 cols (stride 8)
    const int r  = tid >> 3;
    const int c0 = tid & 7;
    float mx = -1e30f;
#pragma unroll 8
    for (int i = 0; i < 128; i++)
        mx = fmaxf(mx, scores[r * SS_PITCH + c0 + i * 8]);
#pragma unroll
    for (int o = 1; o < 8; o <<= 1)
        mx = fmaxf(mx, __shfl_xor_sync(0xFFFFFFFF, mx, o));

    float sum = 0.f;
#pragma unroll 8
    for (int i = 0; i < 128; i++) {
        float e = __expf(scores[r * SS_PITCH + c0 + i * 8] - mx);
        scores[r * SS_PITCH + c0 + i * 8] = e;
        sum += e;
    }
#pragma unroll
    for (int o = 1; o < 8; o <<= 1)
        sum += __shfl_xor_sync(0xFFFFFFFF, sum, o);
    if (c0 == 0) red[r] = 1.0f / sum;
    __syncthreads();

    // Write bf16 beta, coalesced (uint2 = 4 bf16)
    __nv_bfloat16* bp = g_beta + ((size_t)b * N_ + nBase) * N_;
#pragma unroll
    for (int i = 0; i < 32; i++) {
        int idx  = i * 256 + tid;
        int row  = idx >> 8;
        int col4 = (idx & 255) * 4;
        float inv = red[row];
        float4 v = *reinterpret_cast<const float4*>(&scores[row * SS_PITCH + col4]);
        uint2 pk;
        reinterpret_cast<__nv_bfloat162*>(&pk)[0] =
            __nv_bfloat162(__float2bfloat16(v.x * inv), __float2bfloat16(v.y * inv));
        reinterpret_cast<__nv_bfloat162*>(&pk)[1] =
            __nv_bfloat162(__float2bfloat16(v.z * inv), __float2bfloat16(v.w * inv));
        *reinterpret_cast<uint2*>(&bp[(size_t)row * N_ + col4]) = pk;
    }
}

// ---------------------------------------------------------------------------
// Kernel 4: bf16 HMMA GEMM  o[b] = beta[b] @ h_fl[b]  (M=1024, N=768, K=1024)
// CTA tile 128x128x32, 8 warps. 4-stage cp.async pipeline, 2 CTAs/SM.
// Epilogue fuses hw_recover + gamma*o + x.
// ---------------------------------------------------------------------------
constexpr int BK_    = 32;
constexpr int NK_    = N_ / BK_;   // 32 k-chunks
constexpr int STAGE_ = 16384;      // 8KB A + 8KB B per stage
constexpr int STGS_  = 4;

__global__ __launch_bounds__(256, 2) void k_o_mma(
    const float* __restrict__ x, const float* __restrict__ gammaP,
    float* __restrict__ out)
{
    extern __shared__ char smem[];
    const uint32_t sbase = smem_u32(smem);

    const int tid  = threadIdx.x;
    const int wid  = tid >> 5;
    const int lane = tid & 31;
    const int wm   = wid & 3;
    const int wn   = wid >> 2;
    const int b     = blockIdx.z;
    const int mBase = blockIdx.y * 128;
    const int cBase = blockIdx.x * 128;

    const __nv_bfloat16* gA = g_beta + ((size_t)b * N_ + mBase) * N_;
    const __nv_bfloat16* gB = g_hT  + ((size_t)b * HC_ + cBase) * N_;

    const int lr = tid >> 2;
    const int lc = tid & 3;

    auto issue = [&](int slot, int kc) {
        const uint32_t aS = sbase + slot * STAGE_;
        const uint32_t bS = aS + 8192;
        const int kOff = kc * BK_ + lc * 8;
#pragma unroll
        for (int i = 0; i < 2; i++) {
            int r = lr + i * 64;
            CP16(aS + swz(r, lc), gA + (size_t)r * N_ + kOff);
        }
#pragma unroll
        for (int i = 0; i < 2; i++) {
            int r = lr + i * 64;
            CP16(bS + swz(r, lc), gB + (size_t)r * N_ + kOff);
        }
    };

    float acc[2][8][4];
#pragma unroll
    for (int mt = 0; mt < 2; mt++)
#pragma unroll
        for (int nt = 0; nt < 8; nt++)
#pragma unroll
            for (int j = 0; j < 4; j++) acc[mt][nt][j] = 0.f;

    issue(0, 0); CPCOMMIT();
    issue(1, 1); CPCOMMIT();
    issue(2, 2); CPCOMMIT();

    for (int kc = 0; kc < NK_; kc++) {
        if (kc + 3 < NK_) {
            issue((kc + 3) % STGS_, kc + 3); CPCOMMIT();
            CPWAIT(3);
        } else {
            CPWAIT(0);
        }
        __syncthreads();

        const uint32_t aS = sbase + (kc % STGS_) * STAGE_;
        const uint32_t bS = aS + 8192;
#pragma unroll
        for (int ks = 0; ks < 2; ks++) {
            uint32_t afr[2][4];
#pragma unroll
            for (int mt = 0; mt < 2; mt++) {
                int row = wm * 32 + mt * 16 + ((lane >> 3) & 1) * 8 + (lane & 7);
                int ch  = ks * 2 + (lane >> 4);
                ldsm_x4(afr[mt][0], afr[mt][1], afr[mt][2], afr[mt][3],
                        aS + swz(row, ch));
            }
            uint32_t bfr[8][2];
#pragma unroll
            for (int p = 0; p < 4; p++) {
                int row = wn * 64 + p * 16 + (lane >> 4) * 8 + (lane & 7);
                int ch  = ks * 2 + ((lane >> 3) & 1);
                uint32_t r0, r1, r2, r3;
                ldsm_x4(r0, r1, r2, r3, bS + swz(row, ch));
                bfr[2 * p][0] = r0; bfr[2 * p][1] = r1;
                bfr[2 * p + 1][0] = r2; bfr[2 * p + 1][1] = r3;
            }
#pragma unroll
            for (int mt = 0; mt < 2; mt++)
#pragma unroll
                for (int nt = 0; nt < 8; nt++)
                    mma_bf16(acc[mt][nt], afr[mt], bfr[nt]);
        }
        __syncthreads();
    }

    const float gamma = __ldg(gammaP);
    const int gr = lane >> 2;
    const int qc = (lane & 3) * 2;
#pragma unroll
    for (int mt = 0; mt < 2; mt++) {
#pragma unroll
        for (int rr = 0; rr < 2; rr++) {
            int m    = mBase + wm * 32 + mt * 16 + rr * 8 + gr;
            int hr   = m >> 8;
            int wpix = m & 255;
#pragma unroll
            for (int nt = 0; nt < 8; nt++) {
                int cg = cBase + wn * 64 + nt * 8 + qc;
                int sg = cg >> 8;
                int ch = cg & 255;
                int hh = sg * HS_ + hr;
                size_t idx = (((size_t)b * H_ + hh) * W_ + wpix) * C_ + ch;
                float2 xv = *reinterpret_cast<const float2*>(x + idx);
                float2 o;
                o.x = fmaf(gamma, acc[mt][nt][rr * 2 + 0], xv.x);
                o.y = fmaf(gamma, acc[mt][nt][rr * 2 + 1], xv.y);
                *reinterpret_cast<float2*>(out + idx) = o;
            }
        }
    }
}

// ---------------------------------------------------------------------------
extern "C" void kernel_launch(void* const* d_in, const int* in_sizes, int n_in,
                              void* d_out, int out_size)
{
    const float* x     = (const float*)d_in[0];
    const float* Wf    = (const float*)d_in[1];
    const float* Wg    = (const float*)d_in[2];
    const float* Wh    = (const float*)d_in[3];
    const float* gamma = (const float*)d_in[4];
    float* out = (float*)d_out;

    static bool attrSet = false;
    if (!attrSet) {
        cudaFuncSetAttribute(k_proj_h, cudaFuncAttributeMaxDynamicSharedMemorySize,
                             PH_STGS * PH_STAGE);
        cudaFuncSetAttribute(k_proj_fg, cudaFuncAttributeMaxDynamicSharedMemorySize,
                             PJ_STGS * PJ_STAGE);
        cudaFuncSetAttribute(k_fused_attn, cudaFuncAttributeMaxDynamicSharedMemorySize,
                             FS_TOTAL);
        cudaFuncSetAttribute(k_o_mma, cudaFuncAttributeMaxDynamicSharedMemorySize,
                             STGS_ * STAGE_);
        attrSet = true;
    }

    k_split_x   <<<P_ * C_ / 4 / 256, 256>>>(x);
    k_split_w   <<<320, 256>>>(Wf, Wg, Wh);
    k_proj_h    <<<dim3(4, P_ / 128), 256, PH_STGS * PH_STAGE>>>();
    k_proj_fg   <<<P_ / 128, 256, PJ_STGS * PJ_STAGE>>>();
    k_fused_attn<<<dim3(N_ / 32, B_), 256, FS_TOTAL>>>();
    k_o_mma     <<<dim3(HC_ / 128, N_ / 128, B_), 256,
                   STGS_ * STAGE_>>>(x, gamma, out);
}

// round 9
// speedup vs baseline: 1.0048x; 1.0048x over previous
#include <cuda_runtime.h>
#include <cuda_bf16.h>
#include <cstdint>

// Problem constants
constexpr int B_  = 32;
constexpr int H_  = 12;
constexpr int W_  = 256;
constexpr int C_  = 256;
constexpr int HS_ = 4;            // H / SPLIT
constexpr int N_  = HS_ * W_;     // 1024 flattened spatial
constexpr int FC_ = 96;           // SPLIT * Cf
constexpr int HC_ = 768;          // SPLIT * C
constexpr int P_  = B_ * H_ * W_; // 98304 pixels

// Scratch (device globals)
__device__ __nv_bfloat16 g_Wthi[320 * 256];             // [j][k] transposed concat
__device__ __nv_bfloat16 g_Wtlo[320 * 256];
__device__ __nv_bfloat16 g_fhi[(size_t)B_ * N_ * FC_];  // 6.3 MB each
__device__ __nv_bfloat16 g_flo[(size_t)B_ * N_ * FC_];
__device__ __nv_bfloat16 g_ghi[(size_t)B_ * N_ * FC_];
__device__ __nv_bfloat16 g_glo[(size_t)B_ * N_ * FC_];
__device__ float g_s[(size_t)B_ * N_ * N_];             // 134 MB
__device__ __nv_bfloat16 g_beta[(size_t)B_ * N_ * N_];  // 64 MB  [b][n][m]
__device__ __nv_bfloat16 g_hT[(size_t)B_ * HC_ * N_];   // 48 MB  [b][c][n]

// ============================ PTX helpers ==================================
__device__ __forceinline__ uint32_t smem_u32(const void* p) {
    uint32_t a;
    asm("{ .reg .u64 t; cvta.to.shared.u64 t, %1; cvt.u32.u64 %0, t; }"
        : "=r"(a) : "l"(p));
    return a;
}
#define CP16(s, g) \
    asm volatile("cp.async.cg.shared.global [%0], [%1], 16;" \
        :: "r"(s), "l"(g) : "memory")
#define CPCOMMIT() asm volatile("cp.async.commit_group;" ::: "memory")
#define CPWAIT(n)  asm volatile("cp.async.wait_group %0;" :: "n"(n) : "memory")

__device__ __forceinline__ void ldsm_x4(uint32_t& r0, uint32_t& r1,
                                        uint32_t& r2, uint32_t& r3, uint32_t addr) {
    asm volatile("ldmatrix.sync.aligned.m8n8.x4.shared.b16 {%0,%1,%2,%3}, [%4];"
        : "=r"(r0), "=r"(r1), "=r"(r2), "=r"(r3) : "r"(addr));
}
__device__ __forceinline__ void mma_bf16(float* c, const uint32_t* a, const uint32_t* b) {
    asm volatile("mma.sync.aligned.m16n8k16.row.col.f32.bf16.bf16.f32 "
        "{%0,%1,%2,%3}, {%4,%5,%6,%7}, {%8,%9}, {%0,%1,%2,%3};"
        : "+f"(c[0]), "+f"(c[1]), "+f"(c[2]), "+f"(c[3])
        : "r"(a[0]), "r"(a[1]), "r"(a[2]), "r"(a[3]), "r"(b[0]), "r"(b[1]));
}
// smem tile: 64B rows (32 bf16), 4x16B chunks/row, XOR swizzle for ldmatrix
__device__ __forceinline__ uint32_t swz(int r, int c) {
    return (uint32_t)(r * 64 + ((c ^ ((r >> 1) & 3)) << 4));
}
__device__ __forceinline__ void split2(float v, __nv_bfloat16& hi, __nv_bfloat16& lo) {
    hi = __float2bfloat16(v);
    lo = __float2bfloat16(v - __bfloat162float(hi));
}

// ---------------------------------------------------------------------------
// Kernel 0: build transposed split concat weight Wt[j][k], j in [0,320)
// ---------------------------------------------------------------------------
__global__ __launch_bounds__(256) void k_split_w(
    const float* __restrict__ Wf, const float* __restrict__ Wg,
    const float* __restrict__ Wh)
{
    const int j = blockIdx.x;
    const int k = threadIdx.x;
    float v;
    if (j < 256)      v = Wh[k * 256 + j];
    else if (j < 288) v = Wf[k * 32 + (j - 256)];
    else              v = Wg[k * 32 + (j - 288)];
    __nv_bfloat16 hi, lo;
    split2(v, hi, lo);
    g_Wthi[j * 256 + k] = hi;
    g_Wtlo[j * 256 + k] = lo;
}

// ---------------------------------------------------------------------------
// Kernel 1a: h projection, 1-pass bf16 HMMA, consumes fp32 x directly
// (in-kernel convert, no split_x pass). Tile 128(p) x 64(c), K=256.
// Epilogue: transpose in smem -> coalesced g_hT write.
// ---------------------------------------------------------------------------
constexpr int PHF_PITCH = 144;                // fp32 stage row pitch (bytes)
constexpr int PHF_A   = 128 * PHF_PITCH;      // 18432
constexpr int PH_STAGE = PHF_A + 4096;        // + B bf16 4KB = 22528
constexpr int PH_STGS  = 3;
constexpr int PH_ABF   = PH_STGS * PH_STAGE;  // converted A bf16 (8KB)
constexpr int PH_TOTAL = PH_ABF + 8192;
constexpr int TS_ = 136;                      // transpose staging pitch (bf16)

__global__ __launch_bounds__(256) void k_proj_h(const float* __restrict__ x)
{
    extern __shared__ char smem[];
    const uint32_t sbase = smem_u32(smem);
    const uint32_t aBf = sbase + PH_ABF;
    const int tid  = threadIdx.x;
    const int wid  = tid >> 5;
    const int lane = tid & 31;
    const int wm   = wid & 3;
    const int wn   = wid >> 2;
    const int cBase = blockIdx.x * 64;     // 0..3 -> channels 0..255
    const int pBase = blockIdx.y * 128;

    const __nv_bfloat16* gBh = g_Wthi + (size_t)cBase * 256;
    const int arow = tid >> 2, ac = tid & 3;

    auto issue = [&](int slot, int kc) {
        const uint32_t st = sbase + slot * PH_STAGE;
#pragma unroll
        for (int i = 0; i < 4; i++) {
            int idx = i * 256 + tid;
            int r = idx >> 3, c4 = idx & 7;
            CP16(st + r * PHF_PITCH + c4 * 16,
                 x + (size_t)(pBase + r) * 256 + kc * 32 + c4 * 4);
        }
        CP16(st + PHF_A + swz(arow, ac), gBh + (size_t)arow * 256 + kc * 32 + ac * 8);
    };

    float acc[2][4][4];
#pragma unroll
    for (int mt = 0; mt < 2; mt++)
#pragma unroll
        for (int nt = 0; nt < 4; nt++)
#pragma unroll
            for (int j = 0; j < 4; j++) acc[mt][nt][j] = 0.f;

    issue(0, 0); CPCOMMIT();
    issue(1, 1); CPCOMMIT();

    for (int kc = 0; kc < 8; kc++) {
        if (kc + 2 < 8) {
            issue((kc + 2) % PH_STGS, kc + 2); CPCOMMIT();
            CPWAIT(2);
        } else {
            CPWAIT(0);
        }
        __syncthreads();
        const char* fst = smem + (kc % PH_STGS) * PH_STAGE;
        // Convert fp32 stage -> bf16 swizzled aBf
#pragma unroll
        for (int i = 0; i < 2; i++) {
            int idx = i * 256 + tid;
            int r = idx >> 2, c8 = idx & 3;
            const float4* p = reinterpret_cast<const float4*>(fst + r * PHF_PITCH + c8 * 32);
            float4 v0 = p[0], v1 = p[1];
            uint4 pk;
            reinterpret_cast<__nv_bfloat162*>(&pk)[0] =
                __nv_bfloat162(__float2bfloat16(v0.x), __float2bfloat16(v0.y));
            reinterpret_cast<__nv_bfloat162*>(&pk)[1] =
                __nv_bfloat162(__float2bfloat16(v0.z), __float2bfloat16(v0.w));
            reinterpret_cast<__nv_bfloat162*>(&pk)[2] =
                __nv_bfloat162(__float2bfloat16(v1.x), __float2bfloat16(v1.y));
            reinterpret_cast<__nv_bfloat162*>(&pk)[3] =
                __nv_bfloat162(__float2bfloat16(v1.z), __float2bfloat16(v1.w));
            *reinterpret_cast<uint4*>(smem + PH_ABF + swz(r, c8)) = pk;
        }
        __syncthreads();

        const uint32_t bT = sbase + (kc % PH_STGS) * PH_STAGE + PHF_A;
#pragma unroll
        for (int ks = 0; ks < 2; ks++) {
            uint32_t ah[2][4];
#pragma unroll
            for (int mt = 0; mt < 2; mt++) {
                int row = wm * 32 + mt * 16 + ((lane >> 3) & 1) * 8 + (lane & 7);
                int ch  = ks * 2 + (lane >> 4);
                ldsm_x4(ah[mt][0], ah[mt][1], ah[mt][2], ah[mt][3], aBf + swz(row, ch));
            }
            uint32_t bh[4][2];
#pragma unroll
            for (int p = 0; p < 2; p++) {
                int row = wn * 32 + p * 16 + (lane >> 4) * 8 + (lane & 7);
                int ch  = ks * 2 + ((lane >> 3) & 1);
                uint32_t r0, r1, r2, r3;
                ldsm_x4(r0, r1, r2, r3, bT + swz(row, ch));
                bh[2 * p][0] = r0; bh[2 * p][1] = r1;
                bh[2 * p + 1][0] = r2; bh[2 * p + 1][1] = r3;
            }
#pragma unroll
            for (int mt = 0; mt < 2; mt++)
#pragma unroll
                for (int nt = 0; nt < 4; nt++)
                    mma_bf16(acc[mt][nt], ah[mt], bh[nt]);
        }
        __syncthreads();
    }

    const int gr = lane >> 2;
    const int qc = (lane & 3) * 2;
    const int bb  = pBase / (H_ * W_);
    const int rem = pBase - bb * (H_ * W_);
    const int hpx = rem >> 8;
    const int w0  = rem & 255;
    const int sg  = hpx >> 2;
    const int hr  = hpx & 3;
    const int n0  = hr * W_ + w0;

    // Stage transposed [c=64][n=128] in smem, write g_hT coalesced
    __nv_bfloat16* ts = reinterpret_cast<__nv_bfloat16*>(smem);
#pragma unroll
    for (int mt = 0; mt < 2; mt++)
#pragma unroll
        for (int rr = 0; rr < 2; rr++) {
            int nl = wm * 32 + mt * 16 + rr * 8 + gr;
#pragma unroll
            for (int nt = 0; nt < 4; nt++) {
                int cl = wn * 32 + nt * 8 + qc;
                ts[cl * TS_ + nl]       = __float2bfloat16(acc[mt][nt][rr * 2 + 0]);
                ts[(cl + 1) * TS_ + nl] = __float2bfloat16(acc[mt][nt][rr * 2 + 1]);
            }
        }
    __syncthreads();
    const size_t hTrow0 = ((size_t)bb * HC_ + sg * 256 + cBase) * N_ + n0;
#pragma unroll
    for (int i = 0; i < 4; i++) {
        int idx = i * 256 + tid;
        int r = idx >> 4, u = idx & 15;
        uint4 v = *reinterpret_cast<const uint4*>(&ts[r * TS_ + u * 8]);
        *reinterpret_cast<uint4*>(&g_hT[hTrow0 + (size_t)r * N_ + u * 8]) = v;
    }
}

// ---------------------------------------------------------------------------
// Kernel 1b: f/g projection, 3-pass bf16 HMMA, consumes fp32 x directly
// (in-kernel hi/lo split). Tile 128(p) x 64(c), K=256.
// ---------------------------------------------------------------------------
constexpr int PJ_STAGE = PHF_A + 8192;        // A fp32 18432 + Bh 4K + Bl 4K
constexpr int PJ_STGS  = 3;
constexpr int PJ_AHI   = PJ_STGS * PJ_STAGE;  // 79872
constexpr int PJ_ALO   = PJ_AHI + 8192;
constexpr int PJ_TOTAL = PJ_ALO + 8192;       // 96256

__global__ __launch_bounds__(256) void k_proj_fg(const float* __restrict__ x)
{
    extern __shared__ char smem[];
    const uint32_t sbase = smem_u32(smem);
    const uint32_t aHi = sbase + PJ_AHI, aLo = sbase + PJ_ALO;
    const int tid  = threadIdx.x;
    const int wid  = tid >> 5;
    const int lane = tid & 31;
    const int wm   = wid & 3;
    const int wn   = wid >> 2;
    const int cBase = 256;                 // f/g columns 256..319
    const int pBase = blockIdx.x * 128;

    const __nv_bfloat16* gBh = g_Wthi + (size_t)cBase * 256;
    const __nv_bfloat16* gBl = g_Wtlo + (size_t)cBase * 256;
    const int arow = tid >> 2, ac = tid & 3;

    auto issue = [&](int slot, int kc) {
        const uint32_t st = sbase + slot * PJ_STAGE;
#pragma unroll
        for (int i = 0; i < 4; i++) {
            int idx = i * 256 + tid;
            int r = idx >> 3, c4 = idx & 7;
            CP16(st + r * PHF_PITCH + c4 * 16,
                 x + (size_t)(pBase + r) * 256 + kc * 32 + c4 * 4);
        }
        CP16(st + PHF_A + swz(arow, ac), gBh + (size_t)arow * 256 + kc * 32 + ac * 8);
        CP16(st + PHF_A + 4096 + swz(arow, ac), gBl + (size_t)arow * 256 + kc * 32 + ac * 8);
    };

    float acc[2][4][4];
#pragma unroll
    for (int mt = 0; mt < 2; mt++)
#pragma unroll
        for (int nt = 0; nt < 4; nt++)
#pragma unroll
            for (int j = 0; j < 4; j++) acc[mt][nt][j] = 0.f;

    issue(0, 0); CPCOMMIT();
    issue(1, 1); CPCOMMIT();

    for (int kc = 0; kc < 8; kc++) {
        if (kc + 2 < 8) {
            issue((kc + 2) % PJ_STGS, kc + 2); CPCOMMIT();
            CPWAIT(2);
        } else {
            CPWAIT(0);
        }
        __syncthreads();
        const char* fst = smem + (kc % PJ_STGS) * PJ_STAGE;
        // Convert fp32 stage -> bf16 hi/lo swizzled buffers
#pragma unroll
        for (int i = 0; i < 2; i++) {
            int idx = i * 256 + tid;
            int r = idx >> 2, c8 = idx & 3;
            const float4* p = reinterpret_cast<const float4*>(fst + r * PHF_PITCH + c8 * 32);
            float4 v0 = p[0], v1 = p[1];
            float vv[8] = {v0.x, v0.y, v0.z, v0.w, v1.x, v1.y, v1.z, v1.w};
            uint4 ph, pl;
            __nv_bfloat16* hb = reinterpret_cast<__nv_bfloat16*>(&ph);
            __nv_bfloat16* lb = reinterpret_cast<__nv_bfloat16*>(&pl);
#pragma unroll
            for (int j = 0; j < 8; j++) split2(vv[j], hb[j], lb[j]);
            *reinterpret_cast<uint4*>(smem + PJ_AHI + swz(r, c8)) = ph;
            *reinterpret_cast<uint4*>(smem + PJ_ALO + swz(r, c8)) = pl;
        }
        __syncthreads();

        const uint32_t bHiT = sbase + (kc % PJ_STGS) * PJ_STAGE + PHF_A;
        const uint32_t bLoT = bHiT + 4096;
#pragma unroll
        for (int ks = 0; ks < 2; ks++) {
            uint32_t ah[2][4], al[2][4];
#pragma unroll
            for (int mt = 0; mt < 2; mt++) {
                int row = wm * 32 + mt * 16 + ((lane >> 3) & 1) * 8 + (lane & 7);
                int ch  = ks * 2 + (lane >> 4);
                ldsm_x4(ah[mt][0], ah[mt][1], ah[mt][2], ah[mt][3], aHi + swz(row, ch));
                ldsm_x4(al[mt][0], al[mt][1], al[mt][2], al[mt][3], aLo + swz(row, ch));
            }
            uint32_t bh[4][2], bl[4][2];
#pragma unroll
            for (int p = 0; p < 2; p++) {
                int row = wn * 32 + p * 16 + (lane >> 4) * 8 + (lane & 7);
                int ch  = ks * 2 + ((lane >> 3) & 1);
                uint32_t r0, r1, r2, r3;
                ldsm_x4(r0, r1, r2, r3, bHiT + swz(row, ch));
                bh[2 * p][0] = r0; bh[2 * p][1] = r1;
                bh[2 * p + 1][0] = r2; bh[2 * p + 1][1] = r3;
                ldsm_x4(r0, r1, r2, r3, bLoT + swz(row, ch));
                bl[2 * p][0] = r0; bl[2 * p][1] = r1;
                bl[2 * p + 1][0] = r2; bl[2 * p + 1][1] = r3;
            }
#pragma unroll
            for (int mt = 0; mt < 2; mt++)
#pragma unroll
                for (int nt = 0; nt < 4; nt++) {
                    mma_bf16(acc[mt][nt], ah[mt], bh[nt]);
                    mma_bf16(acc[mt][nt], ah[mt], bl[nt]);
                    mma_bf16(acc[mt][nt], al[mt], bh[nt]);
                }
        }
        __syncthreads();
    }

    const int gr = lane >> 2;
    const int qc = (lane & 3) * 2;
    const int bb  = pBase / (H_ * W_);
    const int rem = pBase - bb * (H_ * W_);
    const int hpx = rem >> 8;
    const int w0  = rem & 255;
    const int sg  = hpx >> 2;
    const int hr  = hpx & 3;
    const int n0  = hr * W_ + w0;

#pragma unroll
    for (int mt = 0; mt < 2; mt++)
#pragma unroll
        for (int rr = 0; rr < 2; rr++) {
            int nl = wm * 32 + mt * 16 + rr * 8 + gr;
            int n  = n0 + nl;
            size_t base = ((size_t)bb * N_ + n) * FC_ + sg * 32;
#pragma unroll
            for (int nt = 0; nt < 4; nt++) {
                int j = cBase + wn * 32 + nt * 8 + qc;   // 256..319
                float v0 = acc[mt][nt][rr * 2 + 0];
                float v1 = acc[mt][nt][rr * 2 + 1];
                __nv_bfloat16 h0, h1, l0, l1;
                split2(v0, h0, l0); split2(v1, h1, l1);
                __nv_bfloat162 hv(h0, h1), lv(l0, l1);
                if (j < 288) {
                    size_t idx = base + (j - 256);
                    *reinterpret_cast<__nv_bfloat162*>(&g_fhi[idx]) = hv;
                    *reinterpret_cast<__nv_bfloat162*>(&g_flo[idx]) = lv;
                } else {
                    size_t idx = base + (j - 288);
                    *reinterpret_cast<__nv_bfloat162*>(&g_ghi[idx]) = hv;
                    *reinterpret_cast<__nv_bfloat162*>(&g_glo[idx]) = lv;
                }
            }
        }
}

// ---------------------------------------------------------------------------
// Kernel 2: s[b] = g_fl[b] @ f_fl[b]^T via 3-pass bf16 HMMA.
// Tile 128x128, K=96 one-shot (3 subtiles of 32). 8 warps (4m x 2n).
// ---------------------------------------------------------------------------
constexpr int SC_BUF = 24576;   // one operand buffer: 3 subtiles x 8KB

__global__ __launch_bounds__(256) void k_score_mma()
{
    extern __shared__ char smem[];
    const uint32_t sbase = smem_u32(smem);
    const int tid  = threadIdx.x;
    const int wid  = tid >> 5;
    const int lane = tid & 31;
    const int wm   = wid & 3;
    const int wn   = wid >> 2;
    const int b     = blockIdx.z;
    const int mBase = blockIdx.x * 128;   // cols of s (f index)
    const int nBase = blockIdx.y * 128;   // rows of s (g index)

    const __nv_bfloat16* srcs[4] = {
        g_ghi + ((size_t)b * N_ + nBase) * FC_,
        g_glo + ((size_t)b * N_ + nBase) * FC_,
        g_fhi + ((size_t)b * N_ + mBase) * FC_,
        g_flo + ((size_t)b * N_ + mBase) * FC_ };

#pragma unroll
    for (int bf = 0; bf < 4; bf++) {
        const __nv_bfloat16* src = srcs[bf];
        const uint32_t bufS = sbase + bf * SC_BUF;
#pragma unroll
        for (int t = 0; t < 3; t++)
#pragma unroll
            for (int i = 0; i < 2; i++) {
                int idx = i * 256 + tid;
                int r = idx >> 2, c = idx & 3;
                CP16(bufS + t * 8192 + swz(r, c),
                     src + (size_t)r * FC_ + t * 32 + c * 8);
            }
    }
    CPCOMMIT(); CPWAIT(0);
    __syncthreads();

    float acc[2][8][4];
#pragma unroll
    for (int mt = 0; mt < 2; mt++)
#pragma unroll
        for (int nt = 0; nt < 8; nt++)
#pragma unroll
            for (int j = 0; j < 4; j++) acc[mt][nt][j] = 0.f;

    const uint32_t AhS = sbase, AlS = sbase + SC_BUF;
    const uint32_t BhS = sbase + 2 * SC_BUF, BlS = sbase + 3 * SC_BUF;

#pragma unroll
    for (int t = 0; t < 3; t++) {
#pragma unroll
        for (int ks = 0; ks < 2; ks++) {
            uint32_t ah[2][4], al[2][4];
#pragma unroll
            for (int mt = 0; mt < 2; mt++) {
                int row = wm * 32 + mt * 16 + ((lane >> 3) & 1) * 8 + (lane & 7);
                int ch  = ks * 2 + (lane >> 4);
                ldsm_x4(ah[mt][0], ah[mt][1], ah[mt][2], ah[mt][3],
                        AhS + t * 8192 + swz(row, ch));
                ldsm_x4(al[mt][0], al[mt][1], al[mt][2], al[mt][3],
                        AlS + t * 8192 + swz(row, ch));
            }
            uint32_t bh[8][2], bl[8][2];
#pragma unroll
            for (int p = 0; p < 4; p++) {
                int row = wn * 64 + p * 16 + (lane >> 4) * 8 + (lane & 7);
                int ch  = ks * 2 + ((lane >> 3) & 1);
                uint32_t r0, r1, r2, r3;
                ldsm_x4(r0, r1, r2, r3, BhS + t * 8192 + swz(row, ch));
                bh[2 * p][0] = r0; bh[2 * p][1] = r1;
                bh[2 * p + 1][0] = r2; bh[2 * p + 1][1] = r3;
                ldsm_x4(r0, r1, r2, r3, BlS + t * 8192 + swz(row, ch));
                bl[2 * p][0] = r0; bl[2 * p][1] = r1;
                bl[2 * p + 1][0] = r2; bl[2 * p + 1][1] = r3;
            }
#pragma unroll
            for (int mt = 0; mt < 2; mt++)
#pragma unroll
                for (int nt = 0; nt < 8; nt++) {
                    mma_bf16(acc[mt][nt], ah[mt], bh[nt]);
                    mma_bf16(acc[mt][nt], ah[mt], bl[nt]);
                    mma_bf16(acc[mt][nt], al[mt], bh[nt]);
                }
        }
    }

    float* sp = g_s + (size_t)b * N_ * N_;
    const int gr = lane >> 2;
    const int qc = (lane & 3) * 2;
#pragma unroll
    for (int mt = 0; mt < 2; mt++)
#pragma unroll
        for (int rr = 0; rr < 2; rr++) {
            int n = nBase + wm * 32 + mt * 16 + rr * 8 + gr;
#pragma unroll
            for (int nt = 0; nt < 8; nt++) {
                int m = mBase + wn * 64 + nt * 8 + qc;
                float2 v = make_float2(acc[mt][nt][rr * 2], acc[mt][nt][rr * 2 + 1]);
                *reinterpret_cast<float2*>(&sp[(size_t)n * N_ + m]) = v;
            }
        }
}

// ---------------------------------------------------------------------------
// Kernel 3: row softmax (float4 + shuffle reductions); writes bf16 beta
// ---------------------------------------------------------------------------
__global__ __launch_bounds__(256) void k_softmax()
{
    const size_t row = blockIdx.x;
    const float4* sp4 = reinterpret_cast<const float4*>(g_s + row * N_);
    const int tid = threadIdx.x;
    const int lane = tid & 31, warp = tid >> 5;
    __shared__ float red[8];

    float4 v = sp4[tid];
    float m = fmaxf(fmaxf(v.x, v.y), fmaxf(v.z, v.w));
#pragma unroll
    for (int o = 16; o > 0; o >>= 1)
        m = fmaxf(m, __shfl_xor_sync(0xFFFFFFFF, m, o));
    if (lane == 0) red[warp] = m;
    __syncthreads();
    m = red[lane & 7];
#pragma unroll
    for (int o = 4; o > 0; o >>= 1)
        m = fmaxf(m, __shfl_xor_sync(0xFFFFFFFF, m, o));

    float e0 = __expf(v.x - m), e1 = __expf(v.y - m);
    float e2 = __expf(v.z - m), e3 = __expf(v.w - m);
    float s = e0 + e1 + e2 + e3;
#pragma unroll
    for (int o = 16; o > 0; o >>= 1)
        s += __shfl_xor_sync(0xFFFFFFFF, s, o);
    __syncthreads();
    if (lane == 0) red[warp] = s;
    __syncthreads();
    s = red[lane & 7];
#pragma unroll
    for (int o = 4; o > 0; o >>= 1)
        s += __shfl_xor_sync(0xFFFFFFFF, s, o);
    float inv = 1.0f / s;

    uint2 pk;
    reinterpret_cast<__nv_bfloat162*>(&pk)[0] =
        __nv_bfloat162(__float2bfloat16(e0 * inv), __float2bfloat16(e1 * inv));
    reinterpret_cast<__nv_bfloat162*>(&pk)[1] =
        __nv_bfloat162(__float2bfloat16(e2 * inv), __float2bfloat16(e3 * inv));
    reinterpret_cast<uint2*>(g_beta + row * N_)[tid] = pk;
}

// ---------------------------------------------------------------------------
// Kernel 4: bf16 HMMA GEMM  o[b] = beta[b] @ h_fl[b]  (M=1024, N=768, K=1024)
// CTA tile 128x128x32, 8 warps. 4-stage cp.async pipeline.
// Epilogue fuses hw_recover + gamma*o + x.
// ---------------------------------------------------------------------------
constexpr int BK_    = 32;
constexpr int NK_    = N_ / BK_;   // 32 k-chunks
constexpr int STAGE_ = 16384;      // 8KB A + 8KB B per stage
constexpr int STGS_  = 4;

__global__ __launch_bounds__(256) void k_o_mma(
    const float* __restrict__ x, const float* __restrict__ gammaP,
    float* __restrict__ out)
{
    extern __shared__ char smem[];
    const uint32_t sbase = smem_u32(smem);

    const int tid  = threadIdx.x;
    const int wid  = tid >> 5;
    const int lane = tid & 31;
    const int wm   = wid & 3;
    const int wn   = wid >> 2;
    const int b     = blockIdx.z;
    const int mBase = blockIdx.y * 128;
    const int cBase = blockIdx.x * 128;

    const __nv_bfloat16* gA = g_beta + ((size_t)b * N_ + mBase) * N_;
    const __nv_bfloat16* gB = g_hT  + ((size_t)b * HC_ + cBase) * N_;

    const int lr = tid >> 2;
    const int lc = tid & 3;

    auto issue = [&](int slot, int kc) {
        const uint32_t aS = sbase + slot * STAGE_;
        const uint32_t bS = aS + 8192;
        const int kOff = kc * BK_ + lc * 8;
#pragma unroll
        for (int i = 0; i < 2; i++) {
            int r = lr + i * 64;
            CP16(aS + swz(r, lc), gA + (size_t)r * N_ + kOff);
        }
#pragma unroll
        for (int i = 0; i < 2; i++) {
            int r = lr + i * 64;
            CP16(bS + swz(r, lc), gB + (size_t)r * N_ + kOff);
        }
    };

    float acc[2][8][4];
#pragma unroll
    for (int mt = 0; mt < 2; mt++)
#pragma unroll
        for (int nt = 0; nt < 8; nt++)
#pragma unroll
            for (int j = 0; j < 4; j++) acc[mt][nt][j] = 0.f;

    issue(0, 0); CPCOMMIT();
    issue(1, 1); CPCOMMIT();
    issue(2, 2); CPCOMMIT();

    for (int kc = 0; kc < NK_; kc++) {
        if (kc + 3 < NK_) {
            issue((kc + 3) % STGS_, kc + 3); CPCOMMIT();
            CPWAIT(3);
        } else {
            CPWAIT(0);
        }
        __syncthreads();

        const uint32_t aS = sbase + (kc % STGS_) * STAGE_;
        const uint32_t bS = aS + 8192;
#pragma unroll
        for (int ks = 0; ks < 2; ks++) {
            uint32_t afr[2][4];
#pragma unroll
            for (int mt = 0; mt < 2; mt++) {
                int row = wm * 32 + mt * 16 + ((lane >> 3) & 1) * 8 + (lane & 7);
                int ch  = ks * 2 + (lane >> 4);
                ldsm_x4(afr[mt][0], afr[mt][1], afr[mt][2], afr[mt][3],
                        aS + swz(row, ch));
            }
            uint32_t bfr[8][2];
#pragma unroll
            for (int p = 0; p < 4; p++) {
                int row = wn * 64 + p * 16 + (lane >> 4) * 8 + (lane & 7);
                int ch  = ks * 2 + ((lane >> 3) & 1);
                uint32_t r0, r1, r2, r3;
                ldsm_x4(r0, r1, r2, r3, bS + swz(row, ch));
                bfr[2 * p][0] = r0; bfr[2 * p][1] = r1;
                bfr[2 * p + 1][0] = r2; bfr[2 * p + 1][1] = r3;
            }
#pragma unroll
            for (int mt = 0; mt < 2; mt++)
#pragma unroll
                for (int nt = 0; nt < 8; nt++)
                    mma_bf16(acc[mt][nt], afr[mt], bfr[nt]);
        }
        __syncthreads();
    }

    const float gamma = __ldg(gammaP);
    const int gr = lane >> 2;
    const int qc = (lane & 3) * 2;
#pragma unroll
    for (int mt = 0; mt < 2; mt++) {
#pragma unroll
        for (int rr = 0; rr < 2; rr++) {
            int m    = mBase + wm * 32 + mt * 16 + rr * 8 + gr;
            int hr   = m >> 8;
            int wpix = m & 255;
#pragma unroll
            for (int nt = 0; nt < 8; nt++) {
                int cg = cBase + wn * 64 + nt * 8 + qc;
                int sg = cg >> 8;
                int ch = cg & 255;
                int hh = sg * HS_ + hr;
                size_t idx = (((size_t)b * H_ + hh) * W_ + wpix) * C_ + ch;
                float2 xv = *reinterpret_cast<const float2*>(x + idx);
                float2 o;
                o.x = fmaf(gamma, acc[mt][nt][rr * 2 + 0], xv.x);
                o.y = fmaf(gamma, acc[mt][nt][rr * 2 + 1], xv.y);
                *reinterpret_cast<float2*>(out + idx) = o;
            }
        }
    }
}

// ---------------------------------------------------------------------------
extern "C" void kernel_launch(void* const* d_in, const int* in_sizes, int n_in,
                              void* d_out, int out_size)
{
    const float* x     = (const float*)d_in[0];
    const float* Wf    = (const float*)d_in[1];
    const float* Wg    = (const float*)d_in[2];
    const float* Wh    = (const float*)d_in[3];
    const float* gamma = (const float*)d_in[4];
    float* out = (float*)d_out;

    static bool attrSet = false;
    if (!attrSet) {
        cudaFuncSetAttribute(k_proj_h, cudaFuncAttributeMaxDynamicSharedMemorySize,
                             PH_TOTAL);
        cudaFuncSetAttribute(k_proj_fg, cudaFuncAttributeMaxDynamicSharedMemorySize,
                             PJ_TOTAL);
        cudaFuncSetAttribute(k_score_mma, cudaFuncAttributeMaxDynamicSharedMemorySize,
                             4 * SC_BUF);
        cudaFuncSetAttribute(k_o_mma, cudaFuncAttributeMaxDynamicSharedMemorySize,
                             STGS_ * STAGE_);
        attrSet = true;
    }

    k_split_w  <<<320, 256>>>(Wf, Wg, Wh);
    k_proj_h   <<<dim3(4, P_ / 128), 256, PH_TOTAL>>>(x);
    k_proj_fg  <<<P_ / 128, 256, PJ_TOTAL>>>(x);
    k_score_mma<<<dim3(N_ / 128, N_ / 128, B_), 256, 4 * SC_BUF>>>();
    k_softmax  <<<dim3(B_ * N_), 256>>>();
    k_o_mma    <<<dim3(HC_ / 128, N_ / 128, B_), 256,
                  STGS_ * STAGE_>>>(x, gamma, out);
}

// round 10
// speedup vs baseline: 1.0856x; 1.0804x over previous
#include <cuda_runtime.h>
#include <cuda_bf16.h>
#include <cuda_fp16.h>
#include <cstdint>

// Problem constants
constexpr int B_  = 32;
constexpr int H_  = 12;
constexpr int W_  = 256;
constexpr int C_  = 256;
constexpr int HS_ = 4;            // H / SPLIT
constexpr int N_  = HS_ * W_;     // 1024 flattened spatial
constexpr int FC_ = 96;           // SPLIT * Cf
constexpr int HC_ = 768;          // SPLIT * C
constexpr int P_  = B_ * H_ * W_; // 98304 pixels

// Scratch (device globals)
__device__ __nv_bfloat16 g_xhi[(size_t)P_ * C_];        // 50 MB
__device__ __nv_bfloat16 g_xlo[(size_t)P_ * C_];        // 50 MB
__device__ __nv_bfloat16 g_Wthi[320 * 256];             // [j][k] transposed concat
__device__ __nv_bfloat16 g_Wtlo[320 * 256];
__device__ __half g_f16[(size_t)B_ * N_ * FC_];         // 6.3 MB fp16
__device__ __half g_g16[(size_t)B_ * N_ * FC_];         // 6.3 MB fp16
__device__ float g_s[(size_t)B_ * N_ * N_];             // 134 MB
__device__ __nv_bfloat16 g_beta[(size_t)B_ * N_ * N_];  // 64 MB  [b][n][m]
__device__ __nv_bfloat16 g_hT[(size_t)B_ * HC_ * N_];   // 48 MB  [b][c][n]

// ============================ PTX helpers ==================================
__device__ __forceinline__ uint32_t smem_u32(const void* p) {
    uint32_t a;
    asm("{ .reg .u64 t; cvta.to.shared.u64 t, %1; cvt.u32.u64 %0, t; }"
        : "=r"(a) : "l"(p));
    return a;
}
#define CP16(s, g) \
    asm volatile("cp.async.cg.shared.global [%0], [%1], 16;" \
        :: "r"(s), "l"(g) : "memory")
#define CPCOMMIT() asm volatile("cp.async.commit_group;" ::: "memory")
#define CPWAIT(n)  asm volatile("cp.async.wait_group %0;" :: "n"(n) : "memory")

__device__ __forceinline__ void ldsm_x4(uint32_t& r0, uint32_t& r1,
                                        uint32_t& r2, uint32_t& r3, uint32_t addr) {
    asm volatile("ldmatrix.sync.aligned.m8n8.x4.shared.b16 {%0,%1,%2,%3}, [%4];"
        : "=r"(r0), "=r"(r1), "=r"(r2), "=r"(r3) : "r"(addr));
}
__device__ __forceinline__ void mma_bf16(float* c, const uint32_t* a, const uint32_t* b) {
    asm volatile("mma.sync.aligned.m16n8k16.row.col.f32.bf16.bf16.f32 "
        "{%0,%1,%2,%3}, {%4,%5,%6,%7}, {%8,%9}, {%0,%1,%2,%3};"
        : "+f"(c[0]), "+f"(c[1]), "+f"(c[2]), "+f"(c[3])
        : "r"(a[0]), "r"(a[1]), "r"(a[2]), "r"(a[3]), "r"(b[0]), "r"(b[1]));
}
__device__ __forceinline__ void mma_fp16(float* c, const uint32_t* a, const uint32_t* b) {
    asm volatile("mma.sync.aligned.m16n8k16.row.col.f32.f16.f16.f32 "
        "{%0,%1,%2,%3}, {%4,%5,%6,%7}, {%8,%9}, {%0,%1,%2,%3};"
        : "+f"(c[0]), "+f"(c[1]), "+f"(c[2]), "+f"(c[3])
        : "r"(a[0]), "r"(a[1]), "r"(a[2]), "r"(a[3]), "r"(b[0]), "r"(b[1]));
}
// smem tile: 64B rows (32 x b16), 4x16B chunks/row, XOR swizzle for ldmatrix
__device__ __forceinline__ uint32_t swz(int r, int c) {
    return (uint32_t)(r * 64 + ((c ^ ((r >> 1) & 3)) << 4));
}
__device__ __forceinline__ void split2(float v, __nv_bfloat16& hi, __nv_bfloat16& lo) {
    hi = __float2bfloat16(v);
    lo = __float2bfloat16(v - __bfloat162float(hi));
}

// ---------------------------------------------------------------------------
// Kernel 0a: split x into bf16 hi/lo
// ---------------------------------------------------------------------------
__global__ __launch_bounds__(256) void k_split_x(const float* __restrict__ x)
{
    size_t gid = (size_t)blockIdx.x * 256 + threadIdx.x;   // float4 index
    float4 v = reinterpret_cast<const float4*>(x)[gid];
    __nv_bfloat16 h0, h1, h2, h3, l0, l1, l2, l3;
    split2(v.x, h0, l0); split2(v.y, h1, l1);
    split2(v.z, h2, l2); split2(v.w, h3, l3);
    uint2 hu, lu;
    reinterpret_cast<__nv_bfloat162*>(&hu)[0] = __nv_bfloat162(h0, h1);
    reinterpret_cast<__nv_bfloat162*>(&hu)[1] = __nv_bfloat162(h2, h3);
    reinterpret_cast<__nv_bfloat162*>(&lu)[0] = __nv_bfloat162(l0, l1);
    reinterpret_cast<__nv_bfloat162*>(&lu)[1] = __nv_bfloat162(l2, l3);
    reinterpret_cast<uint2*>(g_xhi)[gid] = hu;
    reinterpret_cast<uint2*>(g_xlo)[gid] = lu;
}

// ---------------------------------------------------------------------------
// Kernel 0b: build transposed split concat weight Wt[j][k], j in [0,320)
// ---------------------------------------------------------------------------
__global__ __launch_bounds__(256) void k_split_w(
    const float* __restrict__ Wf, const float* __restrict__ Wg,
    const float* __restrict__ Wh)
{
    const int j = blockIdx.x;
    const int k = threadIdx.x;
    float v;
    if (j < 256)      v = Wh[k * 256 + j];
    else if (j < 288) v = Wf[k * 32 + (j - 256)];
    else              v = Wg[k * 32 + (j - 288)];
    __nv_bfloat16 hi, lo;
    split2(v, hi, lo);
    g_Wthi[j * 256 + k] = hi;
    g_Wtlo[j * 256 + k] = lo;
}

// ---------------------------------------------------------------------------
// Kernel 1a: h projection, 1-pass bf16 HMMA.
// Tile 128(p) x 64(c), K=256. 8 warps (4m x 2n).
// Epilogue: transpose in smem -> coalesced g_hT write.
// ---------------------------------------------------------------------------
constexpr int PH_STAGE = 12288;   // Ah 8K + Bh 4K
constexpr int PH_STGS  = 3;
constexpr int TS_ = 136;          // transpose staging pitch (bf16)

__global__ __launch_bounds__(256) void k_proj_h()
{
    extern __shared__ char smem[];
    const uint32_t sbase = smem_u32(smem);
    const int tid  = threadIdx.x;
    const int wid  = tid >> 5;
    const int lane = tid & 31;
    const int wm   = wid & 3;
    const int wn   = wid >> 2;
    const int cBase = blockIdx.x * 64;     // 0..3 -> channels 0..255
    const int pBase = blockIdx.y * 128;

    const __nv_bfloat16* gAh = g_xhi + (size_t)pBase * 256;
    const __nv_bfloat16* gBh = g_Wthi + (size_t)cBase * 256;

    const int arow = tid >> 2, ac = tid & 3;
    auto issue = [&](int slot, int kc) {
        const uint32_t st = sbase + slot * PH_STAGE;
#pragma unroll
        for (int i = 0; i < 2; i++) {
            int idx = i * 256 + tid;
            int r = idx >> 2, c = idx & 3;
            CP16(st + swz(r, c), gAh + (size_t)r * 256 + kc * 32 + c * 8);
        }
        if (arow < 64)
            CP16(st + 8192 + swz(arow, ac), gBh + (size_t)arow * 256 + kc * 32 + ac * 8);
    };

    float acc[2][4][4];
#pragma unroll
    for (int mt = 0; mt < 2; mt++)
#pragma unroll
        for (int nt = 0; nt < 4; nt++)
#pragma unroll
            for (int j = 0; j < 4; j++) acc[mt][nt][j] = 0.f;

    issue(0, 0); CPCOMMIT();
    issue(1, 1); CPCOMMIT();

    for (int kc = 0; kc < 8; kc++) {
        if (kc + 2 < 8) {
            issue((kc + 2) % PH_STGS, kc + 2); CPCOMMIT();
            CPWAIT(2);
        } else {
            CPWAIT(0);
        }
        __syncthreads();
        const uint32_t st = sbase + (kc % PH_STGS) * PH_STAGE;
#pragma unroll
        for (int ks = 0; ks < 2; ks++) {
            uint32_t ah[2][4];
#pragma unroll
            for (int mt = 0; mt < 2; mt++) {
                int row = wm * 32 + mt * 16 + ((lane >> 3) & 1) * 8 + (lane & 7);
                int ch  = ks * 2 + (lane >> 4);
                ldsm_x4(ah[mt][0], ah[mt][1], ah[mt][2], ah[mt][3], st + swz(row, ch));
            }
            uint32_t bh[4][2];
#pragma unroll
            for (int p = 0; p < 2; p++) {
                int row = wn * 32 + p * 16 + (lane >> 4) * 8 + (lane & 7);
                int ch  = ks * 2 + ((lane >> 3) & 1);
                uint32_t r0, r1, r2, r3;
                ldsm_x4(r0, r1, r2, r3, st + 8192 + swz(row, ch));
                bh[2 * p][0] = r0; bh[2 * p][1] = r1;
                bh[2 * p + 1][0] = r2; bh[2 * p + 1][1] = r3;
            }
#pragma unroll
            for (int mt = 0; mt < 2; mt++)
#pragma unroll
                for (int nt = 0; nt < 4; nt++)
                    mma_bf16(acc[mt][nt], ah[mt], bh[nt]);
        }
        __syncthreads();
    }

    const int gr = lane >> 2;
    const int qc = (lane & 3) * 2;
    const int bb  = pBase / (H_ * W_);
    const int rem = pBase - bb * (H_ * W_);
    const int hpx = rem >> 8;
    const int w0  = rem & 255;
    const int sg  = hpx >> 2;
    const int hr  = hpx & 3;
    const int n0  = hr * W_ + w0;

    __nv_bfloat16* ts = reinterpret_cast<__nv_bfloat16*>(smem);
#pragma unroll
    for (int mt = 0; mt < 2; mt++)
#pragma unroll
        for (int rr = 0; rr < 2; rr++) {
            int nl = wm * 32 + mt * 16 + rr * 8 + gr;
#pragma unroll
            for (int nt = 0; nt < 4; nt++) {
                int cl = wn * 32 + nt * 8 + qc;
                ts[cl * TS_ + nl]       = __float2bfloat16(acc[mt][nt][rr * 2 + 0]);
                ts[(cl + 1) * TS_ + nl] = __float2bfloat16(acc[mt][nt][rr * 2 + 1]);
            }
        }
    __syncthreads();
    const size_t hTrow0 = ((size_t)bb * HC_ + sg * 256 + cBase) * N_ + n0;
#pragma unroll
    for (int i = 0; i < 4; i++) {
        int idx = i * 256 + tid;
        int r = idx >> 4, u = idx & 15;
        uint4 v = *reinterpret_cast<const uint4*>(&ts[r * TS_ + u * 8]);
        *reinterpret_cast<uint4*>(&g_hT[hTrow0 + (size_t)r * N_ + u * 8]) = v;
    }
}

// ---------------------------------------------------------------------------
// Kernel 1b: f/g projection via 3-pass bf16 HMMA (accurate), stores fp16.
// Tile 128(p) x 64(c: f 32 + g 32), K=256. 8 warps (4m x 2n).
// ---------------------------------------------------------------------------
constexpr int PJ_STAGE = 24576;   // Ah 8K + Al 8K + Bh 4K + Bl 4K
constexpr int PJ_STGS  = 3;

__global__ __launch_bounds__(256) void k_proj_fg()
{
    extern __shared__ char smem[];
    const uint32_t sbase = smem_u32(smem);
    const int tid  = threadIdx.x;
    const int wid  = tid >> 5;
    const int lane = tid & 31;
    const int wm   = wid & 3;
    const int wn   = wid >> 2;
    const int cBase = 256;                 // f/g columns 256..319
    const int pBase = blockIdx.x * 128;

    const __nv_bfloat16* gAh = g_xhi + (size_t)pBase * 256;
    const __nv_bfloat16* gAl = g_xlo + (size_t)pBase * 256;
    const __nv_bfloat16* gBh = g_Wthi + (size_t)cBase * 256;
    const __nv_bfloat16* gBl = g_Wtlo + (size_t)cBase * 256;

    const int arow = tid >> 2, ac = tid & 3;
    auto issue = [&](int slot, int kc) {
        const uint32_t st = sbase + slot * PJ_STAGE;
        const int kOff = kc * 32 + ac * 8;
#pragma unroll
        for (int i = 0; i < 2; i++) {
            int idx = i * 256 + tid;
            int r = idx >> 2, c = idx & 3;
            int ko = kc * 32 + c * 8;
            CP16(st + swz(r, c), gAh + (size_t)r * 256 + ko);
            CP16(st + 8192 + swz(r, c), gAl + (size_t)r * 256 + ko);
        }
        if (arow < 64) {
            CP16(st + 16384 + swz(arow, ac), gBh + (size_t)arow * 256 + kOff);
            CP16(st + 20480 + swz(arow, ac), gBl + (size_t)arow * 256 + kOff);
        }
    };

    float acc[2][4][4];
#pragma unroll
    for (int mt = 0; mt < 2; mt++)
#pragma unroll
        for (int nt = 0; nt < 4; nt++)
#pragma unroll
            for (int j = 0; j < 4; j++) acc[mt][nt][j] = 0.f;

    issue(0, 0); CPCOMMIT();
    issue(1, 1); CPCOMMIT();

    for (int kc = 0; kc < 8; kc++) {
        if (kc + 2 < 8) {
            issue((kc + 2) % PJ_STGS, kc + 2); CPCOMMIT();
            CPWAIT(2);
        } else {
            CPWAIT(0);
        }
        __syncthreads();
        const uint32_t st = sbase + (kc % PJ_STGS) * PJ_STAGE;
#pragma unroll
        for (int ks = 0; ks < 2; ks++) {
            uint32_t ah[2][4], al[2][4];
#pragma unroll
            for (int mt = 0; mt < 2; mt++) {
                int row = wm * 32 + mt * 16 + ((lane >> 3) & 1) * 8 + (lane & 7);
                int ch  = ks * 2 + (lane >> 4);
                ldsm_x4(ah[mt][0], ah[mt][1], ah[mt][2], ah[mt][3], st + swz(row, ch));
                ldsm_x4(al[mt][0], al[mt][1], al[mt][2], al[mt][3], st + 8192 + swz(row, ch));
            }
            uint32_t bh[4][2], bl[4][2];
#pragma unroll
            for (int p = 0; p < 2; p++) {
                int row = wn * 32 + p * 16 + (lane >> 4) * 8 + (lane & 7);
                int ch  = ks * 2 + ((lane >> 3) & 1);
                uint32_t r0, r1, r2, r3;
                ldsm_x4(r0, r1, r2, r3, st + 16384 + swz(row, ch));
                bh[2 * p][0] = r0; bh[2 * p][1] = r1;
                bh[2 * p + 1][0] = r2; bh[2 * p + 1][1] = r3;
                ldsm_x4(r0, r1, r2, r3, st + 20480 + swz(row, ch));
                bl[2 * p][0] = r0; bl[2 * p][1] = r1;
                bl[2 * p + 1][0] = r2; bl[2 * p + 1][1] = r3;
            }
#pragma unroll
            for (int mt = 0; mt < 2; mt++)
#pragma unroll
                for (int nt = 0; nt < 4; nt++) {
                    mma_bf16(acc[mt][nt], ah[mt], bh[nt]);
                    mma_bf16(acc[mt][nt], ah[mt], bl[nt]);
                    mma_bf16(acc[mt][nt], al[mt], bh[nt]);
                }
        }
        __syncthreads();
    }

    const int gr = lane >> 2;
    const int qc = (lane & 3) * 2;
    const int bb  = pBase / (H_ * W_);
    const int rem = pBase - bb * (H_ * W_);
    const int hpx = rem >> 8;
    const int w0  = rem & 255;
    const int sg  = hpx >> 2;
    const int hr  = hpx & 3;
    const int n0  = hr * W_ + w0;

#pragma unroll
    for (int mt = 0; mt < 2; mt++)
#pragma unroll
        for (int rr = 0; rr < 2; rr++) {
            int nl = wm * 32 + mt * 16 + rr * 8 + gr;
            int n  = n0 + nl;
            size_t base = ((size_t)bb * N_ + n) * FC_ + sg * 32;
#pragma unroll
            for (int nt = 0; nt < 4; nt++) {
                int j = cBase + wn * 32 + nt * 8 + qc;   // 256..319
                __half2 hv = __float22half2_rn(
                    make_float2(acc[mt][nt][rr * 2 + 0], acc[mt][nt][rr * 2 + 1]));
                if (j < 288)
                    *reinterpret_cast<__half2*>(&g_f16[base + (j - 256)]) = hv;
                else
                    *reinterpret_cast<__half2*>(&g_g16[base + (j - 288)]) = hv;
            }
        }
}

// ---------------------------------------------------------------------------
// Kernel 2: s[b] = g_fl[b] @ f_fl[b]^T via SINGLE-PASS fp16 HMMA.
// Tile 128x128, K=96 one-shot (3 subtiles of 32). 8 warps (4m x 2n).
// smem 48 KB -> 4 CTAs/SM.
// ---------------------------------------------------------------------------
constexpr int SC_BUF = 24576;   // one operand buffer: 3 subtiles x 8KB

__global__ __launch_bounds__(256) void k_score_mma()
{
    extern __shared__ char smem[];
    const uint32_t sbase = smem_u32(smem);
    const int tid  = threadIdx.x;
    const int wid  = tid >> 5;
    const int lane = tid & 31;
    const int wm   = wid & 3;
    const int wn   = wid >> 2;
    const int b     = blockIdx.z;
    const int mBase = blockIdx.x * 128;   // cols of s (f index)
    const int nBase = blockIdx.y * 128;   // rows of s (g index)

    const __half* srcA = g_g16 + ((size_t)b * N_ + nBase) * FC_;
    const __half* srcB = g_f16 + ((size_t)b * N_ + mBase) * FC_;

    const uint32_t AS = sbase, BS = sbase + SC_BUF;
#pragma unroll
    for (int t = 0; t < 3; t++)
#pragma unroll
        for (int i = 0; i < 2; i++) {
            int idx = i * 256 + tid;
            int r = idx >> 2, c = idx & 3;
            CP16(AS + t * 8192 + swz(r, c), srcA + (size_t)r * FC_ + t * 32 + c * 8);
            CP16(BS + t * 8192 + swz(r, c), srcB + (size_t)r * FC_ + t * 32 + c * 8);
        }
    CPCOMMIT(); CPWAIT(0);
    __syncthreads();

    float acc[2][8][4];
#pragma unroll
    for (int mt = 0; mt < 2; mt++)
#pragma unroll
        for (int nt = 0; nt < 8; nt++)
#pragma unroll
            for (int j = 0; j < 4; j++) acc[mt][nt][j] = 0.f;

#pragma unroll
    for (int t = 0; t < 3; t++) {
#pragma unroll
        for (int ks = 0; ks < 2; ks++) {
            uint32_t af[2][4];
#pragma unroll
            for (int mt = 0; mt < 2; mt++) {
                int row = wm * 32 + mt * 16 + ((lane >> 3) & 1) * 8 + (lane & 7);
                int ch  = ks * 2 + (lane >> 4);
                ldsm_x4(af[mt][0], af[mt][1], af[mt][2], af[mt][3],
                        AS + t * 8192 + swz(row, ch));
            }
            uint32_t bf[8][2];
#pragma unroll
            for (int p = 0; p < 4; p++) {
                int row = wn * 64 + p * 16 + (lane >> 4) * 8 + (lane & 7);
                int ch  = ks * 2 + ((lane >> 3) & 1);
                uint32_t r0, r1, r2, r3;
                ldsm_x4(r0, r1, r2, r3, BS + t * 8192 + swz(row, ch));
                bf[2 * p][0] = r0; bf[2 * p][1] = r1;
                bf[2 * p + 1][0] = r2; bf[2 * p + 1][1] = r3;
            }
#pragma unroll
            for (int mt = 0; mt < 2; mt++)
#pragma unroll
                for (int nt = 0; nt < 8; nt++)
                    mma_fp16(acc[mt][nt], af[mt], bf[nt]);
        }
    }

    float* sp = g_s + (size_t)b * N_ * N_;
    const int gr = lane >> 2;
    const int qc = (lane & 3) * 2;
#pragma unroll
    for (int mt = 0; mt < 2; mt++)
#pragma unroll
        for (int rr = 0; rr < 2; rr++) {
            int n = nBase + wm * 32 + mt * 16 + rr * 8 + gr;
#pragma unroll
            for (int nt = 0; nt < 8; nt++) {
                int m = mBase + wn * 64 + nt * 8 + qc;
                float2 v = make_float2(acc[mt][nt][rr * 2], acc[mt][nt][rr * 2 + 1]);
                *reinterpret_cast<float2*>(&sp[(size_t)n * N_ + m]) = v;
            }
        }
}

// ---------------------------------------------------------------------------
// Kernel 3: row softmax (float4 + shuffle reductions); writes bf16 beta
// ---------------------------------------------------------------------------
__global__ __launch_bounds__(256) void k_softmax()
{
    const size_t row = blockIdx.x;
    const float4* sp4 = reinterpret_cast<const float4*>(g_s + row * N_);
    const int tid = threadIdx.x;
    const int lane = tid & 31, warp = tid >> 5;
    __shared__ float red[8];

    float4 v = sp4[tid];
    float m = fmaxf(fmaxf(v.x, v.y), fmaxf(v.z, v.w));
#pragma unroll
    for (int o = 16; o > 0; o >>= 1)
        m = fmaxf(m, __shfl_xor_sync(0xFFFFFFFF, m, o));
    if (lane == 0) red[warp] = m;
    __syncthreads();
    m = red[lane & 7];
#pragma unroll
    for (int o = 4; o > 0; o >>= 1)
        m = fmaxf(m, __shfl_xor_sync(0xFFFFFFFF, m, o));

    float e0 = __expf(v.x - m), e1 = __expf(v.y - m);
    float e2 = __expf(v.z - m), e3 = __expf(v.w - m);
    float s = e0 + e1 + e2 + e3;
#pragma unroll
    for (int o = 16; o > 0; o >>= 1)
        s += __shfl_xor_sync(0xFFFFFFFF, s, o);
    __syncthreads();
    if (lane == 0) red[warp] = s;
    __syncthreads();
    s = red[lane & 7];
#pragma unroll
    for (int o = 4; o > 0; o >>= 1)
        s += __shfl_xor_sync(0xFFFFFFFF, s, o);
    float inv = 1.0f / s;

    uint2 pk;
    reinterpret_cast<__nv_bfloat162*>(&pk)[0] =
        __nv_bfloat162(__float2bfloat16(e0 * inv), __float2bfloat16(e1 * inv));
    reinterpret_cast<__nv_bfloat162*>(&pk)[1] =
        __nv_bfloat162(__float2bfloat16(e2 * inv), __float2bfloat16(e3 * inv));
    reinterpret_cast<uint2*>(g_beta + row * N_)[tid] = pk;
}

// ---------------------------------------------------------------------------
// Kernel 4: bf16 HMMA GEMM  o[b] = beta[b] @ h_fl[b]  (M=1024, N=768, K=1024)
// CTA tile 128x128x32, 8 warps. 4-stage cp.async pipeline.
// Epilogue fuses hw_recover + gamma*o + x.
// ---------------------------------------------------------------------------
constexpr int BK_    = 32;
constexpr int NK_    = N_ / BK_;   // 32 k-chunks
constexpr int STAGE_ = 16384;      // 8KB A + 8KB B per stage
constexpr int STGS_  = 4;

__global__ __launch_bounds__(256) void k_o_mma(
    const float* __restrict__ x, const float* __restrict__ gammaP,
    float* __restrict__ out)
{
    extern __shared__ char smem[];
    const uint32_t sbase = smem_u32(smem);

    const int tid  = threadIdx.x;
    const int wid  = tid >> 5;
    const int lane = tid & 31;
    const int wm   = wid & 3;
    const int wn   = wid >> 2;
    const int b     = blockIdx.z;
    const int mBase = blockIdx.y * 128;
    const int cBase = blockIdx.x * 128;

    const __nv_bfloat16* gA = g_beta + ((size_t)b * N_ + mBase) * N_;
    const __nv_bfloat16* gB = g_hT  + ((size_t)b * HC_ + cBase) * N_;

    const int lr = tid >> 2;
    const int lc = tid & 3;

    auto issue = [&](int slot, int kc) {
        const uint32_t aS = sbase + slot * STAGE_;
        const uint32_t bS = aS + 8192;
        const int kOff = kc * BK_ + lc * 8;
#pragma unroll
        for (int i = 0; i < 2; i++) {
            int r = lr + i * 64;
            CP16(aS + swz(r, lc), gA + (size_t)r * N_ + kOff);
        }
#pragma unroll
        for (int i = 0; i < 2; i++) {
            int r = lr + i * 64;
            CP16(bS + swz(r, lc), gB + (size_t)r * N_ + kOff);
        }
    };

    float acc[2][8][4];
#pragma unroll
    for (int mt = 0; mt < 2; mt++)
#pragma unroll
        for (int nt = 0; nt < 8; nt++)
#pragma unroll
            for (int j = 0; j < 4; j++) acc[mt][nt][j] = 0.f;

    issue(0, 0); CPCOMMIT();
    issue(1, 1); CPCOMMIT();
    issue(2, 2); CPCOMMIT();

    for (int kc = 0; kc < NK_; kc++) {
        if (kc + 3 < NK_) {
            issue((kc + 3) % STGS_, kc + 3); CPCOMMIT();
            CPWAIT(3);
        } else {
            CPWAIT(0);
        }
        __syncthreads();

        const uint32_t aS = sbase + (kc % STGS_) * STAGE_;
        const uint32_t bS = aS + 8192;
#pragma unroll
        for (int ks = 0; ks < 2; ks++) {
            uint32_t afr[2][4];
#pragma unroll
            for (int mt = 0; mt < 2; mt++) {
                int row = wm * 32 + mt * 16 + ((lane >> 3) & 1) * 8 + (lane & 7);
                int ch  = ks * 2 + (lane >> 4);
                ldsm_x4(afr[mt][0], afr[mt][1], afr[mt][2], afr[mt][3],
                        aS + swz(row, ch));
            }
            uint32_t bfr[8][2];
#pragma unroll
            for (int p = 0; p < 4; p++) {
                int row = wn * 64 + p * 16 + (lane >> 4) * 8 + (lane & 7);
                int ch  = ks * 2 + ((lane >> 3) & 1);
                uint32_t r0, r1, r2, r3;
                ldsm_x4(r0, r1, r2, r3, bS + swz(row, ch));
                bfr[2 * p][0] = r0; bfr[2 * p][1] = r1;
                bfr[2 * p + 1][0] = r2; bfr[2 * p + 1][1] = r3;
            }
#pragma unroll
            for (int mt = 0; mt < 2; mt++)
#pragma unroll
                for (int nt = 0; nt < 8; nt++)
                    mma_bf16(acc[mt][nt], afr[mt], bfr[nt]);
        }
        __syncthreads();
    }

    const float gamma = __ldg(gammaP);
    const int gr = lane >> 2;
    const int qc = (lane & 3) * 2;
#pragma unroll
    for (int mt = 0; mt < 2; mt++) {
#pragma unroll
        for (int rr = 0; rr < 2; rr++) {
            int m    = mBase + wm * 32 + mt * 16 + rr * 8 + gr;
            int hr   = m >> 8;
            int wpix = m & 255;
#pragma unroll
            for (int nt = 0; nt < 8; nt++) {
                int cg = cBase + wn * 64 + nt * 8 + qc;
                int sg = cg >> 8;
                int ch = cg & 255;
                int hh = sg * HS_ + hr;
                size_t idx = (((size_t)b * H_ + hh) * W_ + wpix) * C_ + ch;
                float2 xv = *reinterpret_cast<const float2*>(x + idx);
                float2 o;
                o.x = fmaf(gamma, acc[mt][nt][rr * 2 + 0], xv.x);
                o.y = fmaf(gamma, acc[mt][nt][rr * 2 + 1], xv.y);
                *reinterpret_cast<float2*>(out + idx) = o;
            }
        }
    }
}

// ---------------------------------------------------------------------------
extern "C" void kernel_launch(void* const* d_in, const int* in_sizes, int n_in,
                              void* d_out, int out_size)
{
    const float* x     = (const float*)d_in[0];
    const float* Wf    = (const float*)d_in[1];
    const float* Wg    = (const float*)d_in[2];
    const float* Wh    = (const float*)d_in[3];
    const float* gamma = (const float*)d_in[4];
    float* out = (float*)d_out;

    static bool attrSet = false;
    if (!attrSet) {
        cudaFuncSetAttribute(k_proj_h, cudaFuncAttributeMaxDynamicSharedMemorySize,
                             PH_STGS * PH_STAGE);
        cudaFuncSetAttribute(k_proj_fg, cudaFuncAttributeMaxDynamicSharedMemorySize,
                             PJ_STGS * PJ_STAGE);
        cudaFuncSetAttribute(k_score_mma, cudaFuncAttributeMaxDynamicSharedMemorySize,
                             2 * SC_BUF);
        cudaFuncSetAttribute(k_o_mma, cudaFuncAttributeMaxDynamicSharedMemorySize,
                             STGS_ * STAGE_);
        attrSet = true;
    }

    k_split_x  <<<P_ * C_ / 4 / 256, 256>>>(x);
    k_split_w  <<<320, 256>>>(Wf, Wg, Wh);
    k_proj_h   <<<dim3(4, P_ / 128), 256, PH_STGS * PH_STAGE>>>();
    k_proj_fg  <<<P_ / 128, 256, PJ_STGS * PJ_STAGE>>>();
    k_score_mma<<<dim3(N_ / 128, N_ / 128, B_), 256, 2 * SC_BUF>>>();
    k_softmax  <<<dim3(B_ * N_), 256>>>();
    k_o_mma    <<<dim3(HC_ / 128, N_ / 128, B_), 256,
                  STGS_ * STAGE_>>>(x, gamma, out);
}

// round 11
// speedup vs baseline: 1.2222x; 1.1258x over previous
#include <cuda_runtime.h>
#include <cuda_bf16.h>
#include <cuda_fp16.h>
#include <cstdint>

// Problem constants
constexpr int B_  = 32;
constexpr int H_  = 12;
constexpr int W_  = 256;
constexpr int C_  = 256;
constexpr int HS_ = 4;            // H / SPLIT
constexpr int N_  = HS_ * W_;     // 1024 flattened spatial
constexpr int FC_ = 96;           // SPLIT * Cf
constexpr int HC_ = 768;          // SPLIT * C
constexpr int P_  = B_ * H_ * W_; // 98304 pixels

// Scratch (device globals) — all fp16 now
__device__ __half g_x16[(size_t)P_ * C_];          // 50 MB
__device__ __half g_Wt16[320 * 256];               // transposed concat [j][k]
__device__ __half g_f16[(size_t)B_ * N_ * FC_];    // 6.3 MB
__device__ __half g_g16[(size_t)B_ * N_ * FC_];    // 6.3 MB
__device__ float  g_s[(size_t)B_ * N_ * N_];       // 134 MB
__device__ __half g_beta[(size_t)B_ * N_ * N_];    // 64 MB  [b][n][m]
__device__ __half g_hT[(size_t)B_ * HC_ * N_];     // 48 MB  [b][c][n]

// ============================ PTX helpers ==================================
__device__ __forceinline__ uint32_t smem_u32(const void* p) {
    uint32_t a;
    asm("{ .reg .u64 t; cvta.to.shared.u64 t, %1; cvt.u32.u64 %0, t; }"
        : "=r"(a) : "l"(p));
    return a;
}
#define CP16(s, g) \
    asm volatile("cp.async.cg.shared.global [%0], [%1], 16;" \
        :: "r"(s), "l"(g) : "memory")
#define CPCOMMIT() asm volatile("cp.async.commit_group;" ::: "memory")
#define CPWAIT(n)  asm volatile("cp.async.wait_group %0;" :: "n"(n) : "memory")

__device__ __forceinline__ void ldsm_x4(uint32_t& r0, uint32_t& r1,
                                        uint32_t& r2, uint32_t& r3, uint32_t addr) {
    asm volatile("ldmatrix.sync.aligned.m8n8.x4.shared.b16 {%0,%1,%2,%3}, [%4];"
        : "=r"(r0), "=r"(r1), "=r"(r2), "=r"(r3) : "r"(addr));
}
__device__ __forceinline__ void mma_fp16(float* c, const uint32_t* a, const uint32_t* b) {
    asm volatile("mma.sync.aligned.m16n8k16.row.col.f32.f16.f16.f32 "
        "{%0,%1,%2,%3}, {%4,%5,%6,%7}, {%8,%9}, {%0,%1,%2,%3};"
        : "+f"(c[0]), "+f"(c[1]), "+f"(c[2]), "+f"(c[3])
        : "r"(a[0]), "r"(a[1]), "r"(a[2]), "r"(a[3]), "r"(b[0]), "r"(b[1]));
}
// smem tile: 64B rows (32 x b16), 4x16B chunks/row, XOR swizzle for ldmatrix
__device__ __forceinline__ uint32_t swz(int r, int c) {
    return (uint32_t)(r * 64 + ((c ^ ((r >> 1) & 3)) << 4));
}

// ---------------------------------------------------------------------------
// Kernel 0a: convert x -> fp16
// ---------------------------------------------------------------------------
__global__ __launch_bounds__(256) void k_cvt_x(const float* __restrict__ x)
{
    size_t gid = (size_t)blockIdx.x * 256 + threadIdx.x;   // float4 index
    float4 v = reinterpret_cast<const float4*>(x)[gid];
    uint2 pk;
    reinterpret_cast<__half2*>(&pk)[0] = __float22half2_rn(make_float2(v.x, v.y));
    reinterpret_cast<__half2*>(&pk)[1] = __float22half2_rn(make_float2(v.z, v.w));
    reinterpret_cast<uint2*>(g_x16)[gid] = pk;
}

// ---------------------------------------------------------------------------
// Kernel 0b: build transposed fp16 concat weight Wt[j][k], j in [0,320)
// ---------------------------------------------------------------------------
__global__ __launch_bounds__(256) void k_cvt_w(
    const float* __restrict__ Wf, const float* __restrict__ Wg,
    const float* __restrict__ Wh)
{
    const int j = blockIdx.x;
    const int k = threadIdx.x;
    float v;
    if (j < 256)      v = Wh[k * 256 + j];
    else if (j < 288) v = Wf[k * 32 + (j - 256)];
    else              v = Wg[k * 32 + (j - 288)];
    g_Wt16[j * 256 + k] = __float2half(v);
}

// ---------------------------------------------------------------------------
// Kernel 1: merged projections via 1-pass fp16 HMMA.
// C[P,320] = X[P,256] @ Wt^T. Tile 128(p) x 64(c), K=256 in 8 chunks.
// 8 warps (4m x 2n). Epilogue: h-blocks -> smem transpose -> g_hT (fp16);
// f/g block -> fp16 scatter.
// ---------------------------------------------------------------------------
constexpr int PJ_STAGE = 12288;   // A fp16 8K + B fp16 4K
constexpr int PJ_STGS  = 3;
constexpr int TS_ = 136;          // transpose staging pitch (halves)

__global__ __launch_bounds__(256) void k_proj()
{
    extern __shared__ char smem[];
    const uint32_t sbase = smem_u32(smem);
    const int tid  = threadIdx.x;
    const int wid  = tid >> 5;
    const int lane = tid & 31;
    const int wm   = wid & 3;
    const int wn   = wid >> 2;
    const int cBase = blockIdx.x * 64;     // 0..4 (h: 0..3, f/g: 4)
    const int pBase = blockIdx.y * 128;

    const __half* gA = g_x16 + (size_t)pBase * 256;
    const __half* gB = g_Wt16 + (size_t)cBase * 256;

    const int arow = tid >> 2, ac = tid & 3;
    auto issue = [&](int slot, int kc) {
        const uint32_t st = sbase + slot * PJ_STAGE;
#pragma unroll
        for (int i = 0; i < 2; i++) {
            int idx = i * 256 + tid;
            int r = idx >> 2, c = idx & 3;
            CP16(st + swz(r, c), gA + (size_t)r * 256 + kc * 32 + c * 8);
        }
        CP16(st + 8192 + swz(arow, ac), gB + (size_t)arow * 256 + kc * 32 + ac * 8);
    };

    float acc[2][4][4];
#pragma unroll
    for (int mt = 0; mt < 2; mt++)
#pragma unroll
        for (int nt = 0; nt < 4; nt++)
#pragma unroll
            for (int j = 0; j < 4; j++) acc[mt][nt][j] = 0.f;

    issue(0, 0); CPCOMMIT();
    issue(1, 1); CPCOMMIT();

    for (int kc = 0; kc < 8; kc++) {
        if (kc + 2 < 8) {
            issue((kc + 2) % PJ_STGS, kc + 2); CPCOMMIT();
            CPWAIT(2);
        } else {
            CPWAIT(0);
        }
        __syncthreads();
        const uint32_t st = sbase + (kc % PJ_STGS) * PJ_STAGE;
#pragma unroll
        for (int ks = 0; ks < 2; ks++) {
            uint32_t af[2][4];
#pragma unroll
            for (int mt = 0; mt < 2; mt++) {
                int row = wm * 32 + mt * 16 + ((lane >> 3) & 1) * 8 + (lane & 7);
                int ch  = ks * 2 + (lane >> 4);
                ldsm_x4(af[mt][0], af[mt][1], af[mt][2], af[mt][3], st + swz(row, ch));
            }
            uint32_t bf[4][2];
#pragma unroll
            for (int p = 0; p < 2; p++) {
                int row = wn * 32 + p * 16 + (lane >> 4) * 8 + (lane & 7);
                int ch  = ks * 2 + ((lane >> 3) & 1);
                uint32_t r0, r1, r2, r3;
                ldsm_x4(r0, r1, r2, r3, st + 8192 + swz(row, ch));
                bf[2 * p][0] = r0; bf[2 * p][1] = r1;
                bf[2 * p + 1][0] = r2; bf[2 * p + 1][1] = r3;
            }
#pragma unroll
            for (int mt = 0; mt < 2; mt++)
#pragma unroll
                for (int nt = 0; nt < 4; nt++)
                    mma_fp16(acc[mt][nt], af[mt], bf[nt]);
        }
        __syncthreads();
    }

    // Geometry: 128 consecutive pixels = fixed (b, h), 128 consecutive w.
    const int gr = lane >> 2;
    const int qc = (lane & 3) * 2;
    const int bb  = pBase / (H_ * W_);
    const int rem = pBase - bb * (H_ * W_);
    const int hpx = rem >> 8;
    const int w0  = rem & 255;
    const int sg  = hpx >> 2;
    const int hr  = hpx & 3;
    const int n0  = hr * W_ + w0;

    if (cBase < 256) {
        // h path: stage transposed [c=64][n=128] in smem, write g_hT coalesced
        __half* ts = reinterpret_cast<__half*>(smem);
#pragma unroll
        for (int mt = 0; mt < 2; mt++)
#pragma unroll
            for (int rr = 0; rr < 2; rr++) {
                int nl = wm * 32 + mt * 16 + rr * 8 + gr;
#pragma unroll
                for (int nt = 0; nt < 4; nt++) {
                    int cl = wn * 32 + nt * 8 + qc;
                    ts[cl * TS_ + nl]       = __float2half(acc[mt][nt][rr * 2 + 0]);
                    ts[(cl + 1) * TS_ + nl] = __float2half(acc[mt][nt][rr * 2 + 1]);
                }
            }
        __syncthreads();
        const size_t hTrow0 = ((size_t)bb * HC_ + sg * 256 + cBase) * N_ + n0;
#pragma unroll
        for (int i = 0; i < 4; i++) {
            int idx = i * 256 + tid;
            int r = idx >> 4, u = idx & 15;
            uint4 v = *reinterpret_cast<const uint4*>(&ts[r * TS_ + u * 8]);
            *reinterpret_cast<uint4*>(&g_hT[hTrow0 + (size_t)r * N_ + u * 8]) = v;
        }
    } else {
        // f/g path: fp16 scatter
#pragma unroll
        for (int mt = 0; mt < 2; mt++)
#pragma unroll
            for (int rr = 0; rr < 2; rr++) {
                int nl = wm * 32 + mt * 16 + rr * 8 + gr;
                int n  = n0 + nl;
                size_t base = ((size_t)bb * N_ + n) * FC_ + sg * 32;
#pragma unroll
                for (int nt = 0; nt < 4; nt++) {
                    int j = cBase + wn * 32 + nt * 8 + qc;   // 256..319
                    __half2 hv = __float22half2_rn(
                        make_float2(acc[mt][nt][rr * 2 + 0], acc[mt][nt][rr * 2 + 1]));
                    if (j < 288)
                        *reinterpret_cast<__half2*>(&g_f16[base + (j - 256)]) = hv;
                    else
                        *reinterpret_cast<__half2*>(&g_g16[base + (j - 288)]) = hv;
                }
            }
    }
}

// ---------------------------------------------------------------------------
// Kernel 2: s[b] = g_fl[b] @ f_fl[b]^T via single-pass fp16 HMMA.
// Tile 128x128, K=96 one-shot (3 subtiles of 32). 8 warps (4m x 2n).
// ---------------------------------------------------------------------------
constexpr int SC_BUF = 24576;   // one operand buffer: 3 subtiles x 8KB

__global__ __launch_bounds__(256) void k_score_mma()
{
    extern __shared__ char smem[];
    const uint32_t sbase = smem_u32(smem);
    const int tid  = threadIdx.x;
    const int wid  = tid >> 5;
    const int lane = tid & 31;
    const int wm   = wid & 3;
    const int wn   = wid >> 2;
    const int b     = blockIdx.z;
    const int mBase = blockIdx.x * 128;   // cols of s (f index)
    const int nBase = blockIdx.y * 128;   // rows of s (g index)

    const __half* srcA = g_g16 + ((size_t)b * N_ + nBase) * FC_;
    const __half* srcB = g_f16 + ((size_t)b * N_ + mBase) * FC_;

    const uint32_t AS = sbase, BS = sbase + SC_BUF;
#pragma unroll
    for (int t = 0; t < 3; t++)
#pragma unroll
        for (int i = 0; i < 2; i++) {
            int idx = i * 256 + tid;
            int r = idx >> 2, c = idx & 3;
            CP16(AS + t * 8192 + swz(r, c), srcA + (size_t)r * FC_ + t * 32 + c * 8);
            CP16(BS + t * 8192 + swz(r, c), srcB + (size_t)r * FC_ + t * 32 + c * 8);
        }
    CPCOMMIT(); CPWAIT(0);
    __syncthreads();

    float acc[2][8][4];
#pragma unroll
    for (int mt = 0; mt < 2; mt++)
#pragma unroll
        for (int nt = 0; nt < 8; nt++)
#pragma unroll
            for (int j = 0; j < 4; j++) acc[mt][nt][j] = 0.f;

#pragma unroll
    for (int t = 0; t < 3; t++) {
#pragma unroll
        for (int ks = 0; ks < 2; ks++) {
            uint32_t af[2][4];
#pragma unroll
            for (int mt = 0; mt < 2; mt++) {
                int row = wm * 32 + mt * 16 + ((lane >> 3) & 1) * 8 + (lane & 7);
                int ch  = ks * 2 + (lane >> 4);
                ldsm_x4(af[mt][0], af[mt][1], af[mt][2], af[mt][3],
                        AS + t * 8192 + swz(row, ch));
            }
            uint32_t bf[8][2];
#pragma unroll
            for (int p = 0; p < 4; p++) {
                int row = wn * 64 + p * 16 + (lane >> 4) * 8 + (lane & 7);
                int ch  = ks * 2 + ((lane >> 3) & 1);
                uint32_t r0, r1, r2, r3;
                ldsm_x4(r0, r1, r2, r3, BS + t * 8192 + swz(row, ch));
                bf[2 * p][0] = r0; bf[2 * p][1] = r1;
                bf[2 * p + 1][0] = r2; bf[2 * p + 1][1] = r3;
            }
#pragma unroll
            for (int mt = 0; mt < 2; mt++)
#pragma unroll
                for (int nt = 0; nt < 8; nt++)
                    mma_fp16(acc[mt][nt], af[mt], bf[nt]);
        }
    }

    float* sp = g_s + (size_t)b * N_ * N_;
    const int gr = lane >> 2;
    const int qc = (lane & 3) * 2;
#pragma unroll
    for (int mt = 0; mt < 2; mt++)
#pragma unroll
        for (int rr = 0; rr < 2; rr++) {
            int n = nBase + wm * 32 + mt * 16 + rr * 8 + gr;
#pragma unroll
            for (int nt = 0; nt < 8; nt++) {
                int m = mBase + wn * 64 + nt * 8 + qc;
                float2 v = make_float2(acc[mt][nt][rr * 2], acc[mt][nt][rr * 2 + 1]);
                *reinterpret_cast<float2*>(&sp[(size_t)n * N_ + m]) = v;
            }
        }
}

// ---------------------------------------------------------------------------
// Kernel 3: warp-per-row softmax (8 rows/CTA, no smem, no block syncs);
// writes fp16 beta.
// ---------------------------------------------------------------------------
__global__ __launch_bounds__(256) void k_softmax()
{
    const int wid  = threadIdx.x >> 5;
    const int lane = threadIdx.x & 31;
    const size_t row = (size_t)blockIdx.x * 8 + wid;
    const float4* sp4 = reinterpret_cast<const float4*>(g_s + row * N_);

    float4 v[8];
#pragma unroll
    for (int i = 0; i < 8; i++) v[i] = sp4[lane + 32 * i];

    float m = -1e30f;
#pragma unroll
    for (int i = 0; i < 8; i++)
        m = fmaxf(m, fmaxf(fmaxf(v[i].x, v[i].y), fmaxf(v[i].z, v[i].w)));
#pragma unroll
    for (int o = 16; o > 0; o >>= 1)
        m = fmaxf(m, __shfl_xor_sync(0xFFFFFFFF, m, o));

    float sum = 0.f;
#pragma unroll
    for (int i = 0; i < 8; i++) {
        v[i].x = __expf(v[i].x - m); v[i].y = __expf(v[i].y - m);
        v[i].z = __expf(v[i].z - m); v[i].w = __expf(v[i].w - m);
        sum += (v[i].x + v[i].y) + (v[i].z + v[i].w);
    }
#pragma unroll
    for (int o = 16; o > 0; o >>= 1)
        sum += __shfl_xor_sync(0xFFFFFFFF, sum, o);
    const float inv = 1.0f / sum;

    uint2* bp = reinterpret_cast<uint2*>(g_beta + row * N_);
#pragma unroll
    for (int i = 0; i < 8; i++) {
        uint2 pk;
        reinterpret_cast<__half2*>(&pk)[0] =
            __float22half2_rn(make_float2(v[i].x * inv, v[i].y * inv));
        reinterpret_cast<__half2*>(&pk)[1] =
            __float22half2_rn(make_float2(v[i].z * inv, v[i].w * inv));
        bp[lane + 32 * i] = pk;
    }
}

// ---------------------------------------------------------------------------
// Kernel 4: fp16 HMMA GEMM  o[b] = beta[b] @ h_fl[b]  (M=1024, N=768, K=1024)
// CTA tile 128x128x32, 8 warps. 4-stage cp.async pipeline.
// Epilogue fuses hw_recover + gamma*o + x.
// ---------------------------------------------------------------------------
constexpr int BK_    = 32;
constexpr int NK_    = N_ / BK_;   // 32 k-chunks
constexpr int STAGE_ = 16384;      // 8KB A + 8KB B per stage
constexpr int STGS_  = 4;

__global__ __launch_bounds__(256) void k_o_mma(
    const float* __restrict__ x, const float* __restrict__ gammaP,
    float* __restrict__ out)
{
    extern __shared__ char smem[];
    const uint32_t sbase = smem_u32(smem);

    const int tid  = threadIdx.x;
    const int wid  = tid >> 5;
    const int lane = tid & 31;
    const int wm   = wid & 3;
    const int wn   = wid >> 2;
    const int b     = blockIdx.z;
    const int mBase = blockIdx.y * 128;
    const int cBase = blockIdx.x * 128;

    const __half* gA = g_beta + ((size_t)b * N_ + mBase) * N_;
    const __half* gB = g_hT  + ((size_t)b * HC_ + cBase) * N_;

    const int lr = tid >> 2;
    const int lc = tid & 3;

    auto issue = [&](int slot, int kc) {
        const uint32_t aS = sbase + slot * STAGE_;
        const uint32_t bS = aS + 8192;
        const int kOff = kc * BK_ + lc * 8;
#pragma unroll
        for (int i = 0; i < 2; i++) {
            int r = lr + i * 64;
            CP16(aS + swz(r, lc), gA + (size_t)r * N_ + kOff);
        }
#pragma unroll
        for (int i = 0; i < 2; i++) {
            int r = lr + i * 64;
            CP16(bS + swz(r, lc), gB + (size_t)r * N_ + kOff);
        }
    };

    float acc[2][8][4];
#pragma unroll
    for (int mt = 0; mt < 2; mt++)
#pragma unroll
        for (int nt = 0; nt < 8; nt++)
#pragma unroll
            for (int j = 0; j < 4; j++) acc[mt][nt][j] = 0.f;

    issue(0, 0); CPCOMMIT();
    issue(1, 1); CPCOMMIT();
    issue(2, 2); CPCOMMIT();

    for (int kc = 0; kc < NK_; kc++) {
        if (kc + 3 < NK_) {
            issue((kc + 3) % STGS_, kc + 3); CPCOMMIT();
            CPWAIT(3);
        } else {
            CPWAIT(0);
        }
        __syncthreads();

        const uint32_t aS = sbase + (kc % STGS_) * STAGE_;
        const uint32_t bS = aS + 8192;
#pragma unroll
        for (int ks = 0; ks < 2; ks++) {
            uint32_t afr[2][4];
#pragma unroll
            for (int mt = 0; mt < 2; mt++) {
                int row = wm * 32 + mt * 16 + ((lane >> 3) & 1) * 8 + (lane & 7);
                int ch  = ks * 2 + (lane >> 4);
                ldsm_x4(afr[mt][0], afr[mt][1], afr[mt][2], afr[mt][3],
                        aS + swz(row, ch));
            }
            uint32_t bfr[8][2];
#pragma unroll
            for (int p = 0; p < 4; p++) {
                int row = wn * 64 + p * 16 + (lane >> 4) * 8 + (lane & 7);
                int ch  = ks * 2 + ((lane >> 3) & 1);
                uint32_t r0, r1, r2, r3;
                ldsm_x4(r0, r1, r2, r3, bS + swz(row, ch));
                bfr[2 * p][0] = r0; bfr[2 * p][1] = r1;
                bfr[2 * p + 1][0] = r2; bfr[2 * p + 1][1] = r3;
            }
#pragma unroll
            for (int mt = 0; mt < 2; mt++)
#pragma unroll
                for (int nt = 0; nt < 8; nt++)
                    mma_fp16(acc[mt][nt], afr[mt], bfr[nt]);
        }
        __syncthreads();
    }

    const float gamma = __ldg(gammaP);
    const int gr = lane >> 2;
    const int qc = (lane & 3) * 2;
#pragma unroll
    for (int mt = 0; mt < 2; mt++) {
#pragma unroll
        for (int rr = 0; rr < 2; rr++) {
            int m    = mBase + wm * 32 + mt * 16 + rr * 8 + gr;
            int hr   = m >> 8;
            int wpix = m & 255;
#pragma unroll
            for (int nt = 0; nt < 8; nt++) {
                int cg = cBase + wn * 64 + nt * 8 + qc;
                int sg = cg >> 8;
                int ch = cg & 255;
                int hh = sg * HS_ + hr;
                size_t idx = (((size_t)b * H_ + hh) * W_ + wpix) * C_ + ch;
                float2 xv = *reinterpret_cast<const float2*>(x + idx);
                float2 o;
                o.x = fmaf(gamma, acc[mt][nt][rr * 2 + 0], xv.x);
                o.y = fmaf(gamma, acc[mt][nt][rr * 2 + 1], xv.y);
                *reinterpret_cast<float2*>(out + idx) = o;
            }
        }
    }
}

// ---------------------------------------------------------------------------
extern "C" void kernel_launch(void* const* d_in, const int* in_sizes, int n_in,
                              void* d_out, int out_size)
{
    const float* x     = (const float*)d_in[0];
    const float* Wf    = (const float*)d_in[1];
    const float* Wg    = (const float*)d_in[2];
    const float* Wh    = (const float*)d_in[3];
    const float* gamma = (const float*)d_in[4];
    float* out = (float*)d_out;

    static bool attrSet = false;
    if (!attrSet) {
        cudaFuncSetAttribute(k_proj, cudaFuncAttributeMaxDynamicSharedMemorySize,
                             PJ_STGS * PJ_STAGE);
        cudaFuncSetAttribute(k_score_mma, cudaFuncAttributeMaxDynamicSharedMemorySize,
                             2 * SC_BUF);
        cudaFuncSetAttribute(k_o_mma, cudaFuncAttributeMaxDynamicSharedMemorySize,
                             STGS_ * STAGE_);
        attrSet = true;
    }

    k_cvt_x    <<<P_ * C_ / 4 / 256, 256>>>(x);
    k_cvt_w    <<<320, 256>>>(Wf, Wg, Wh);
    k_proj     <<<dim3(5, P_ / 128), 256, PJ_STGS * PJ_STAGE>>>();
    k_score_mma<<<dim3(N_ / 128, N_ / 128, B_), 256, 2 * SC_BUF>>>();
    k_softmax  <<<B_ * N_ / 8, 256>>>();
    k_o_mma    <<<dim3(HC_ / 128, N_ / 128, B_), 256,
                  STGS_ * STAGE_>>>(x, gamma, out);
}

// round 12
// speedup vs baseline: 1.2758x; 1.0439x over previous
#include <cuda_runtime.h>
#include <cuda_bf16.h>
#include <cuda_fp16.h>
#include <cstdint>

// Problem constants
constexpr int B_  = 32;
constexpr int H_  = 12;
constexpr int W_  = 256;
constexpr int C_  = 256;
constexpr int HS_ = 4;            // H / SPLIT
constexpr int N_  = HS_ * W_;     // 1024 flattened spatial
constexpr int FC_ = 96;           // SPLIT * Cf
constexpr int HC_ = 768;          // SPLIT * C
constexpr int P_  = B_ * H_ * W_; // 98304 pixels

// Scratch (device globals) — all fp16
__device__ __half g_x16[(size_t)P_ * C_];          // 50 MB
__device__ __half g_Wt16[320 * 256];               // transposed concat [j][k]
__device__ __half g_f16[(size_t)B_ * N_ * FC_];    // 6.3 MB
__device__ __half g_g16[(size_t)B_ * N_ * FC_];    // 6.3 MB
__device__ __half g_s[(size_t)B_ * N_ * N_];       // 67 MB fp16 logits
__device__ __half g_beta[(size_t)B_ * N_ * N_];    // 64 MB  [b][n][m]
__device__ __half g_hT[(size_t)B_ * HC_ * N_];     // 48 MB  [b][c][n]

// ============================ PTX helpers ==================================
__device__ __forceinline__ uint32_t smem_u32(const void* p) {
    uint32_t a;
    asm("{ .reg .u64 t; cvta.to.shared.u64 t, %1; cvt.u32.u64 %0, t; }"
        : "=r"(a) : "l"(p));
    return a;
}
#define CP16(s, g) \
    asm volatile("cp.async.cg.shared.global [%0], [%1], 16;" \
        :: "r"(s), "l"(g) : "memory")
#define CPCOMMIT() asm volatile("cp.async.commit_group;" ::: "memory")
#define CPWAIT(n)  asm volatile("cp.async.wait_group %0;" :: "n"(n) : "memory")

__device__ __forceinline__ void ldsm_x4(uint32_t& r0, uint32_t& r1,
                                        uint32_t& r2, uint32_t& r3, uint32_t addr) {
    asm volatile("ldmatrix.sync.aligned.m8n8.x4.shared.b16 {%0,%1,%2,%3}, [%4];"
        : "=r"(r0), "=r"(r1), "=r"(r2), "=r"(r3) : "r"(addr));
}
__device__ __forceinline__ void mma_fp16(float* c, const uint32_t* a, const uint32_t* b) {
    asm volatile("mma.sync.aligned.m16n8k16.row.col.f32.f16.f16.f32 "
        "{%0,%1,%2,%3}, {%4,%5,%6,%7}, {%8,%9}, {%0,%1,%2,%3};"
        : "+f"(c[0]), "+f"(c[1]), "+f"(c[2]), "+f"(c[3])
        : "r"(a[0]), "r"(a[1]), "r"(a[2]), "r"(a[3]), "r"(b[0]), "r"(b[1]));
}
// smem tile: 64B rows (32 x b16), 4x16B chunks/row, XOR swizzle for ldmatrix
__device__ __forceinline__ uint32_t swz(int r, int c) {
    return (uint32_t)(r * 64 + ((c ^ ((r >> 1) & 3)) << 4));
}

// ---------------------------------------------------------------------------
// Kernel 0a: convert x -> fp16
// ---------------------------------------------------------------------------
__global__ __launch_bounds__(256) void k_cvt_x(const float* __restrict__ x)
{
    size_t gid = (size_t)blockIdx.x * 256 + threadIdx.x;   // float4 index
    float4 v = reinterpret_cast<const float4*>(x)[gid];
    uint2 pk;
    reinterpret_cast<__half2*>(&pk)[0] = __float22half2_rn(make_float2(v.x, v.y));
    reinterpret_cast<__half2*>(&pk)[1] = __float22half2_rn(make_float2(v.z, v.w));
    reinterpret_cast<uint2*>(g_x16)[gid] = pk;
}

// ---------------------------------------------------------------------------
// Kernel 0b: build transposed fp16 concat weight Wt[j][k], j in [0,320)
// ---------------------------------------------------------------------------
__global__ __launch_bounds__(256) void k_cvt_w(
    const float* __restrict__ Wf, const float* __restrict__ Wg,
    const float* __restrict__ Wh)
{
    const int j = blockIdx.x;
    const int k = threadIdx.x;
    float v;
    if (j < 256)      v = Wh[k * 256 + j];
    else if (j < 288) v = Wf[k * 32 + (j - 256)];
    else              v = Wg[k * 32 + (j - 288)];
    g_Wt16[j * 256 + k] = __float2half(v);
}

// ---------------------------------------------------------------------------
// Kernel 1: merged projections via 1-pass fp16 HMMA.
// C[P,320] = X[P,256] @ Wt^T. Tile 128(p) x 64(c), K=256 in 8 chunks.
// 8 warps (4m x 2n). Epilogue: h-blocks -> smem transpose -> g_hT (fp16);
// f/g block -> fp16 scatter.
// ---------------------------------------------------------------------------
constexpr int PJ_STAGE = 12288;   // A fp16 8K + B fp16 4K
constexpr int PJ_STGS  = 3;
constexpr int TS_ = 136;          // transpose staging pitch (halves)

__global__ __launch_bounds__(256) void k_proj()
{
    extern __shared__ char smem[];
    const uint32_t sbase = smem_u32(smem);
    const int tid  = threadIdx.x;
    const int wid  = tid >> 5;
    const int lane = tid & 31;
    const int wm   = wid & 3;
    const int wn   = wid >> 2;
    const int cBase = blockIdx.x * 64;     // 0..4 (h: 0..3, f/g: 4)
    const int pBase = blockIdx.y * 128;

    const __half* gA = g_x16 + (size_t)pBase * 256;
    const __half* gB = g_Wt16 + (size_t)cBase * 256;

    const int arow = tid >> 2, ac = tid & 3;
    auto issue = [&](int slot, int kc) {
        const uint32_t st = sbase + slot * PJ_STAGE;
#pragma unroll
        for (int i = 0; i < 2; i++) {
            int idx = i * 256 + tid;
            int r = idx >> 2, c = idx & 3;
            CP16(st + swz(r, c), gA + (size_t)r * 256 + kc * 32 + c * 8);
        }
        CP16(st + 8192 + swz(arow, ac), gB + (size_t)arow * 256 + kc * 32 + ac * 8);
    };

    float acc[2][4][4];
#pragma unroll
    for (int mt = 0; mt < 2; mt++)
#pragma unroll
        for (int nt = 0; nt < 4; nt++)
#pragma unroll
            for (int j = 0; j < 4; j++) acc[mt][nt][j] = 0.f;

    issue(0, 0); CPCOMMIT();
    issue(1, 1); CPCOMMIT();

    for (int kc = 0; kc < 8; kc++) {
        if (kc + 2 < 8) {
            issue((kc + 2) % PJ_STGS, kc + 2); CPCOMMIT();
            CPWAIT(2);
        } else {
            CPWAIT(0);
        }
        __syncthreads();
        const uint32_t st = sbase + (kc % PJ_STGS) * PJ_STAGE;
#pragma unroll
        for (int ks = 0; ks < 2; ks++) {
            uint32_t af[2][4];
#pragma unroll
            for (int mt = 0; mt < 2; mt++) {
                int row = wm * 32 + mt * 16 + ((lane >> 3) & 1) * 8 + (lane & 7);
                int ch  = ks * 2 + (lane >> 4);
                ldsm_x4(af[mt][0], af[mt][1], af[mt][2], af[mt][3], st + swz(row, ch));
            }
            uint32_t bf[4][2];
#pragma unroll
            for (int p = 0; p < 2; p++) {
                int row = wn * 32 + p * 16 + (lane >> 4) * 8 + (lane & 7);
                int ch  = ks * 2 + ((lane >> 3) & 1);
                uint32_t r0, r1, r2, r3;
                ldsm_x4(r0, r1, r2, r3, st + 8192 + swz(row, ch));
                bf[2 * p][0] = r0; bf[2 * p][1] = r1;
                bf[2 * p + 1][0] = r2; bf[2 * p + 1][1] = r3;
            }
#pragma unroll
            for (int mt = 0; mt < 2; mt++)
#pragma unroll
                for (int nt = 0; nt < 4; nt++)
                    mma_fp16(acc[mt][nt], af[mt], bf[nt]);
        }
        __syncthreads();
    }

    // Geometry: 128 consecutive pixels = fixed (b, h), 128 consecutive w.
    const int gr = lane >> 2;
    const int qc = (lane & 3) * 2;
    const int bb  = pBase / (H_ * W_);
    const int rem = pBase - bb * (H_ * W_);
    const int hpx = rem >> 8;
    const int w0  = rem & 255;
    const int sg  = hpx >> 2;
    const int hr  = hpx & 3;
    const int n0  = hr * W_ + w0;

    if (cBase < 256) {
        // h path: stage transposed [c=64][n=128] in smem, write g_hT coalesced
        __half* ts = reinterpret_cast<__half*>(smem);
#pragma unroll
        for (int mt = 0; mt < 2; mt++)
#pragma unroll
            for (int rr = 0; rr < 2; rr++) {
                int nl = wm * 32 + mt * 16 + rr * 8 + gr;
#pragma unroll
                for (int nt = 0; nt < 4; nt++) {
                    int cl = wn * 32 + nt * 8 + qc;
                    ts[cl * TS_ + nl]       = __float2half(acc[mt][nt][rr * 2 + 0]);
                    ts[(cl + 1) * TS_ + nl] = __float2half(acc[mt][nt][rr * 2 + 1]);
                }
            }
        __syncthreads();
        const size_t hTrow0 = ((size_t)bb * HC_ + sg * 256 + cBase) * N_ + n0;
#pragma unroll
        for (int i = 0; i < 4; i++) {
            int idx = i * 256 + tid;
            int r = idx >> 4, u = idx & 15;
            uint4 v = *reinterpret_cast<const uint4*>(&ts[r * TS_ + u * 8]);
            *reinterpret_cast<uint4*>(&g_hT[hTrow0 + (size_t)r * N_ + u * 8]) = v;
        }
    } else {
        // f/g path: fp16 scatter
#pragma unroll
        for (int mt = 0; mt < 2; mt++)
#pragma unroll
            for (int rr = 0; rr < 2; rr++) {
                int nl = wm * 32 + mt * 16 + rr * 8 + gr;
                int n  = n0 + nl;
                size_t base = ((size_t)bb * N_ + n) * FC_ + sg * 32;
#pragma unroll
                for (int nt = 0; nt < 4; nt++) {
                    int j = cBase + wn * 32 + nt * 8 + qc;   // 256..319
                    __half2 hv = __float22half2_rn(
                        make_float2(acc[mt][nt][rr * 2 + 0], acc[mt][nt][rr * 2 + 1]));
                    if (j < 288)
                        *reinterpret_cast<__half2*>(&g_f16[base + (j - 256)]) = hv;
                    else
                        *reinterpret_cast<__half2*>(&g_g16[base + (j - 288)]) = hv;
                }
            }
    }
}

// ---------------------------------------------------------------------------
// Kernel 2: s[b] = g_fl[b] @ f_fl[b]^T via single-pass fp16 HMMA.
// Tile 128x128, K=96 one-shot (3 subtiles of 32). 8 warps (4m x 2n).
// Stores fp16 logits (halved write traffic).
// ---------------------------------------------------------------------------
constexpr int SC_BUF = 24576;   // one operand buffer: 3 subtiles x 8KB

__global__ __launch_bounds__(256) void k_score_mma()
{
    extern __shared__ char smem[];
    const uint32_t sbase = smem_u32(smem);
    const int tid  = threadIdx.x;
    const int wid  = tid >> 5;
    const int lane = tid & 31;
    const int wm   = wid & 3;
    const int wn   = wid >> 2;
    const int b     = blockIdx.z;
    const int mBase = blockIdx.x * 128;   // cols of s (f index)
    const int nBase = blockIdx.y * 128;   // rows of s (g index)

    const __half* srcA = g_g16 + ((size_t)b * N_ + nBase) * FC_;
    const __half* srcB = g_f16 + ((size_t)b * N_ + mBase) * FC_;

    const uint32_t AS = sbase, BS = sbase + SC_BUF;
#pragma unroll
    for (int t = 0; t < 3; t++)
#pragma unroll
        for (int i = 0; i < 2; i++) {
            int idx = i * 256 + tid;
            int r = idx >> 2, c = idx & 3;
            CP16(AS + t * 8192 + swz(r, c), srcA + (size_t)r * FC_ + t * 32 + c * 8);
            CP16(BS + t * 8192 + swz(r, c), srcB + (size_t)r * FC_ + t * 32 + c * 8);
        }
    CPCOMMIT(); CPWAIT(0);
    __syncthreads();

    float acc[2][8][4];
#pragma unroll
    for (int mt = 0; mt < 2; mt++)
#pragma unroll
        for (int nt = 0; nt < 8; nt++)
#pragma unroll
            for (int j = 0; j < 4; j++) acc[mt][nt][j] = 0.f;

#pragma unroll
    for (int t = 0; t < 3; t++) {
#pragma unroll
        for (int ks = 0; ks < 2; ks++) {
            uint32_t af[2][4];
#pragma unroll
            for (int mt = 0; mt < 2; mt++) {
                int row = wm * 32 + mt * 16 + ((lane >> 3) & 1) * 8 + (lane & 7);
                int ch  = ks * 2 + (lane >> 4);
                ldsm_x4(af[mt][0], af[mt][1], af[mt][2], af[mt][3],
                        AS + t * 8192 + swz(row, ch));
            }
            uint32_t bf[8][2];
#pragma unroll
            for (int p = 0; p < 4; p++) {
                int row = wn * 64 + p * 16 + (lane >> 4) * 8 + (lane & 7);
                int ch  = ks * 2 + ((lane >> 3) & 1);
                uint32_t r0, r1, r2, r3;
                ldsm_x4(r0, r1, r2, r3, BS + t * 8192 + swz(row, ch));
                bf[2 * p][0] = r0; bf[2 * p][1] = r1;
                bf[2 * p + 1][0] = r2; bf[2 * p + 1][1] = r3;
            }
#pragma unroll
            for (int mt = 0; mt < 2; mt++)
#pragma unroll
                for (int nt = 0; nt < 8; nt++)
                    mma_fp16(acc[mt][nt], af[mt], bf[nt]);
        }
    }

    __half* sp = g_s + (size_t)b * N_ * N_;
    const int gr = lane >> 2;
    const int qc = (lane & 3) * 2;
#pragma unroll
    for (int mt = 0; mt < 2; mt++)
#pragma unroll
        for (int rr = 0; rr < 2; rr++) {
            int n = nBase + wm * 32 + mt * 16 + rr * 8 + gr;
#pragma unroll
            for (int nt = 0; nt < 8; nt++) {
                int m = mBase + wn * 64 + nt * 8 + qc;
                __half2 v = __float22half2_rn(
                    make_float2(acc[mt][nt][rr * 2], acc[mt][nt][rr * 2 + 1]));
                *reinterpret_cast<__half2*>(&sp[(size_t)n * N_ + m]) = v;
            }
        }
}

// ---------------------------------------------------------------------------
// Kernel 3: warp-per-row softmax over fp16 logits; writes fp16 beta.
// Each lane: 4 x uint4 = 32 halves. No smem, no block syncs.
// ---------------------------------------------------------------------------
__global__ __launch_bounds__(256) void k_softmax()
{
    const int wid  = threadIdx.x >> 5;
    const int lane = threadIdx.x & 31;
    const size_t row = (size_t)blockIdx.x * 8 + wid;
    const uint4* sp = reinterpret_cast<const uint4*>(g_s + row * N_);

    uint4 raw[4];
#pragma unroll
    for (int i = 0; i < 4; i++) raw[i] = sp[lane + 32 * i];

    float v[32];
#pragma unroll
    for (int i = 0; i < 4; i++) {
        const __half2* h2 = reinterpret_cast<const __half2*>(&raw[i]);
#pragma unroll
        for (int j = 0; j < 4; j++) {
            float2 f = __half22float2(h2[j]);
            v[i * 8 + j * 2]     = f.x;
            v[i * 8 + j * 2 + 1] = f.y;
        }
    }

    float m = -1e30f;
#pragma unroll
    for (int i = 0; i < 32; i++) m = fmaxf(m, v[i]);
#pragma unroll
    for (int o = 16; o > 0; o >>= 1)
        m = fmaxf(m, __shfl_xor_sync(0xFFFFFFFF, m, o));

    float sum = 0.f;
#pragma unroll
    for (int i = 0; i < 32; i++) { v[i] = __expf(v[i] - m); sum += v[i]; }
#pragma unroll
    for (int o = 16; o > 0; o >>= 1)
        sum += __shfl_xor_sync(0xFFFFFFFF, sum, o);
    const float inv = 1.0f / sum;

    uint4* bp = reinterpret_cast<uint4*>(g_beta + row * N_);
#pragma unroll
    for (int i = 0; i < 4; i++) {
        uint4 pk;
        __half2* h2 = reinterpret_cast<__half2*>(&pk);
#pragma unroll
        for (int j = 0; j < 4; j++)
            h2[j] = __float22half2_rn(make_float2(v[i * 8 + j * 2] * inv,
                                                  v[i * 8 + j * 2 + 1] * inv));
        bp[lane + 32 * i] = pk;
    }
}

// ---------------------------------------------------------------------------
// Kernel 4: fp16 HMMA GEMM  o[b] = beta[b] @ h_fl[b]  (M=1024, N=768, K=1024)
// CTA tile 128x128x32, 8 warps. 4-stage cp.async pipeline.
// Epilogue fuses hw_recover + gamma*o + x.
// ---------------------------------------------------------------------------
constexpr int BK_    = 32;
constexpr int NK_    = N_ / BK_;   // 32 k-chunks
constexpr int STAGE_ = 16384;      // 8KB A + 8KB B per stage
constexpr int STGS_  = 4;

__global__ __launch_bounds__(256) void k_o_mma(
    const float* __restrict__ x, const float* __restrict__ gammaP,
    float* __restrict__ out)
{
    extern __shared__ char smem[];
    const uint32_t sbase = smem_u32(smem);

    const int tid  = threadIdx.x;
    const int wid  = tid >> 5;
    const int lane = tid & 31;
    const int wm   = wid & 3;
    const int wn   = wid >> 2;
    const int b     = blockIdx.z;
    const int mBase = blockIdx.y * 128;
    const int cBase = blockIdx.x * 128;

    const __half* gA = g_beta + ((size_t)b * N_ + mBase) * N_;
    const __half* gB = g_hT  + ((size_t)b * HC_ + cBase) * N_;

    const int lr = tid >> 2;
    const int lc = tid & 3;

    auto issue = [&](int slot, int kc) {
        const uint32_t aS = sbase + slot * STAGE_;
        const uint32_t bS = aS + 8192;
        const int kOff = kc * BK_ + lc * 8;
#pragma unroll
        for (int i = 0; i < 2; i++) {
            int r = lr + i * 64;
            CP16(aS + swz(r, lc), gA + (size_t)r * N_ + kOff);
        }
#pragma unroll
        for (int i = 0; i < 2; i++) {
            int r = lr + i * 64;
            CP16(bS + swz(r, lc), gB + (size_t)r * N_ + kOff);
        }
    };

    float acc[2][8][4];
#pragma unroll
    for (int mt = 0; mt < 2; mt++)
#pragma unroll
        for (int nt = 0; nt < 8; nt++)
#pragma unroll
            for (int j = 0; j < 4; j++) acc[mt][nt][j] = 0.f;

    issue(0, 0); CPCOMMIT();
    issue(1, 1); CPCOMMIT();
    issue(2, 2); CPCOMMIT();

    for (int kc = 0; kc < NK_; kc++) {
        if (kc + 3 < NK_) {
            issue((kc + 3) % STGS_, kc + 3); CPCOMMIT();
            CPWAIT(3);
        } else {
            CPWAIT(0);
        }
        __syncthreads();

        const uint32_t aS = sbase + (kc % STGS_) * STAGE_;
        const uint32_t bS = aS + 8192;
#pragma unroll
        for (int ks = 0; ks < 2; ks++) {
            uint32_t afr[2][4];
#pragma unroll
            for (int mt = 0; mt < 2; mt++) {
                int row = wm * 32 + mt * 16 + ((lane >> 3) & 1) * 8 + (lane & 7);
                int ch  = ks * 2 + (lane >> 4);
                ldsm_x4(afr[mt][0], afr[mt][1], afr[mt][2], afr[mt][3],
                        aS + swz(row, ch));
            }
            uint32_t bfr[8][2];
#pragma unroll
            for (int p = 0; p < 4; p++) {
                int row = wn * 64 + p * 16 + (lane >> 4) * 8 + (lane & 7);
                int ch  = ks * 2 + ((lane >> 3) & 1);
                uint32_t r0, r1, r2, r3;
                ldsm_x4(r0, r1, r2, r3, bS + swz(row, ch));
                bfr[2 * p][0] = r0; bfr[2 * p][1] = r1;
                bfr[2 * p + 1][0] = r2; bfr[2 * p + 1][1] = r3;
            }
#pragma unroll
            for (int mt = 0; mt < 2; mt++)
#pragma unroll
                for (int nt = 0; nt < 8; nt++)
                    mma_fp16(acc[mt][nt], afr[mt], bfr[nt]);
        }
        __syncthreads();
    }

    const float gamma = __ldg(gammaP);
    const int gr = lane >> 2;
    const int qc = (lane & 3) * 2;
#pragma unroll
    for (int mt = 0; mt < 2; mt++) {
#pragma unroll
        for (int rr = 0; rr < 2; rr++) {
            int m    = mBase + wm * 32 + mt * 16 + rr * 8 + gr;
            int hr   = m >> 8;
            int wpix = m & 255;
#pragma unroll
            for (int nt = 0; nt < 8; nt++) {
                int cg = cBase + wn * 64 + nt * 8 + qc;
                int sg = cg >> 8;
                int ch = cg & 255;
                int hh = sg * HS_ + hr;
                size_t idx = (((size_t)b * H_ + hh) * W_ + wpix) * C_ + ch;
                float2 xv = *reinterpret_cast<const float2*>(x + idx);
                float2 o;
                o.x = fmaf(gamma, acc[mt][nt][rr * 2 + 0], xv.x);
                o.y = fmaf(gamma, acc[mt][nt][rr * 2 + 1], xv.y);
                *reinterpret_cast<float2*>(out + idx) = o;
            }
        }
    }
}

// ---------------------------------------------------------------------------
extern "C" void kernel_launch(void* const* d_in, const int* in_sizes, int n_in,
                              void* d_out, int out_size)
{
    const float* x     = (const float*)d_in[0];
    const float* Wf    = (const float*)d_in[1];
    const float* Wg    = (const float*)d_in[2];
    const float* Wh    = (const float*)d_in[3];
    const float* gamma = (const float*)d_in[4];
    float* out = (float*)d_out;

    static bool attrSet = false;
    if (!attrSet) {
        cudaFuncSetAttribute(k_proj, cudaFuncAttributeMaxDynamicSharedMemorySize,
                             PJ_STGS * PJ_STAGE);
        cudaFuncSetAttribute(k_score_mma, cudaFuncAttributeMaxDynamicSharedMemorySize,
                             2 * SC_BUF);
        cudaFuncSetAttribute(k_o_mma, cudaFuncAttributeMaxDynamicSharedMemorySize,
                             STGS_ * STAGE_);
        attrSet = true;
    }

    k_cvt_x    <<<P_ * C_ / 4 / 256, 256>>>(x);
    k_cvt_w    <<<320, 256>>>(Wf, Wg, Wh);
    k_proj     <<<dim3(5, P_ / 128), 256, PJ_STGS * PJ_STAGE>>>();
    k_score_mma<<<dim3(N_ / 128, N_ / 128, B_), 256, 2 * SC_BUF>>>();
    k_softmax  <<<B_ * N_ / 8, 256>>>();
    k_o_mma    <<<dim3(HC_ / 128, N_ / 128, B_), 256,
                  STGS_ * STAGE_>>>(x, gamma, out);
}